// round 3
// baseline (speedup 1.0000x reference)
#include <cuda_runtime.h>
#include <cstdint>

// Problem-fixed sizes
#define MAX_N 50000
#define MAX_E 800000
#define FIN 128
#define HID 128
#define FOUT 64

// ---------------- scratch (device globals; no allocation allowed) -----------
__device__ __align__(16) float g_h1 [MAX_N * HID];   // x @ W1
__device__ __align__(16) float g_agg[MAX_N * HID];   // relu(aggregate(h1)) + b1
__device__ __align__(16) float g_h2 [MAX_N * FOUT];  // agg @ W2
__device__ float g_dinv[MAX_N];
__device__ int   g_deg [MAX_N];
__device__ int   g_rowstart[MAX_N + 1];
__device__ int   g_cursor[MAX_N];
__device__ int   g_esrc[MAX_E];
__device__ __align__(8) float g_ew[MAX_E];           // dinv[src] per sorted edge
__device__ int   g_bsum[256];
__device__ int   g_is64;                              // edge_index dtype flag

// ---------------- edge dtype probe ------------------------------------------
// If the buffer really is int64, the first 32 values (as int64) are node ids in
// [0, N). If it is int32 data misread as int64, values pack lo + hi*2^32 with hi
// a random node id -> out of range almost surely within 32 samples.
__global__ void k_detect(const void* __restrict__ edges, int N, int E) {
    const long long* p = (const long long*)edges;
    int ok64 = 1;
    int n = (E < 32) ? E : 32;
    for (int i = 0; i < n; i++) {
        long long v = p[i];
        if (v < 0 || v >= N) { ok64 = 0; break; }
    }
    g_is64 = ok64;
}

__device__ __forceinline__ int edge_at(const void* edges, int is64, long long idx) {
    if (is64) return (int)((const long long*)edges)[idx];
    return ((const int*)edges)[idx];
}

// ---------------- degree / CSR build ----------------------------------------
__global__ void k_deg_zero(int N) {
    int i = blockIdx.x * blockDim.x + threadIdx.x;
    if (i < N) g_deg[i] = 0;
}

__global__ void k_deg_count(const void* __restrict__ edges, int E, int N) {
    int e = blockIdx.x * blockDim.x + threadIdx.x;
    if (e < E) {
        int is64 = g_is64;                              // uniform load
        int d = edge_at(edges, is64, (long long)E + e); // dst row
        if ((unsigned)d < (unsigned)N) atomicAdd(&g_deg[d], 1);
    }
}

__global__ void k_dinv(int N) {
    int i = blockIdx.x * blockDim.x + threadIdx.x;
    if (i < N) {
        // +1 for self loop; degree always > 0
        g_dinv[i] = rsqrtf((float)(g_deg[i] + 1));
    }
}

__global__ void k_scan_part(int N) {
    __shared__ int s[256];
    int t = threadIdx.x;
    int i = blockIdx.x * 256 + t;
    int v = (i < N) ? g_deg[i] : 0;
    s[t] = v;
    __syncthreads();
    #pragma unroll
    for (int off = 1; off < 256; off <<= 1) {
        int x = (t >= off) ? s[t - off] : 0;
        __syncthreads();
        s[t] += x;
        __syncthreads();
    }
    if (i < N) g_rowstart[i] = s[t] - v;   // exclusive within block
    if (t == 255) g_bsum[blockIdx.x] = s[255];
}

__global__ void k_scan_mid(int nb) {
    __shared__ int s[256];
    int t = threadIdx.x;
    int v = (t < nb) ? g_bsum[t] : 0;
    s[t] = v;
    __syncthreads();
    #pragma unroll
    for (int off = 1; off < 256; off <<= 1) {
        int x = (t >= off) ? s[t - off] : 0;
        __syncthreads();
        s[t] += x;
        __syncthreads();
    }
    if (t < nb) g_bsum[t] = s[t] - v;      // exclusive block offsets
}

__global__ void k_scan_add(int N, int E) {
    int i = blockIdx.x * 256 + threadIdx.x;
    if (i < N) {
        int r = g_rowstart[i] + g_bsum[blockIdx.x];
        g_rowstart[i] = r;
        g_cursor[i]   = r;
    }
    if (i == 0) g_rowstart[N] = E;
}

__global__ void k_perm(const void* __restrict__ edges, int E, int N) {
    int e = blockIdx.x * blockDim.x + threadIdx.x;
    if (e < E) {
        int is64 = g_is64;
        int s = edge_at(edges, is64, e);
        int d = edge_at(edges, is64, (long long)E + e);
        if ((unsigned)d < (unsigned)N && (unsigned)s < (unsigned)N) {
            int pos = atomicAdd(&g_cursor[d], 1);
            g_esrc[pos] = s;
            g_ew[pos]   = g_dinv[s];
        }
    }
}

// ---------------- fp32 SIMT GEMM: C[M,BN] = A[M,Kd] @ W[Kd,BN] ---------------
template<int BM, int BN, int BK, int TM, int TN>
__device__ __forceinline__ void gemm_dev(const float* __restrict__ A,
                                         const float* __restrict__ W,
                                         float* __restrict__ C,
                                         int M, int Kd) {
    constexpr int THREADS = (BM / TM) * (BN / TN);
    __shared__ float As[BM][BK];
    __shared__ float Ws[BK][BN];
    const int tid  = threadIdx.x;
    const int tm   = (tid / (BN / TN)) * TM;
    const int tn   = (tid % (BN / TN)) * TN;
    const int row0 = blockIdx.x * BM;

    float acc[TM][TN];
    #pragma unroll
    for (int i = 0; i < TM; i++)
        #pragma unroll
        for (int j = 0; j < TN; j++) acc[i][j] = 0.f;

    for (int kc = 0; kc < Kd; kc += BK) {
        // A tile (natural layout, float4 coalesced)
        for (int idx = tid; idx < BM * (BK / 4); idx += THREADS) {
            int m  = idx / (BK / 4);
            int k4 = (idx % (BK / 4)) * 4;
            float4 v = make_float4(0.f, 0.f, 0.f, 0.f);
            int gr = row0 + m;
            if (gr < M)
                v = *reinterpret_cast<const float4*>(A + (size_t)gr * Kd + kc + k4);
            *reinterpret_cast<float4*>(&As[m][k4]) = v;
        }
        // W tile (straight copy)
        for (int idx = tid; idx < BK * (BN / 4); idx += THREADS) {
            reinterpret_cast<float4*>(&Ws[0][0])[idx] =
                reinterpret_cast<const float4*>(W + (size_t)kc * BN)[idx];
        }
        __syncthreads();

        #pragma unroll 8
        for (int k = 0; k < BK; k++) {
            float a[TM], b[TN];
            #pragma unroll
            for (int i = 0; i < TM; i++) a[i] = As[tm + i][k];
            #pragma unroll
            for (int j = 0; j < TN; j += 4)
                *reinterpret_cast<float4*>(&b[j]) =
                    *reinterpret_cast<const float4*>(&Ws[k][tn + j]);
            #pragma unroll
            for (int i = 0; i < TM; i++)
                #pragma unroll
                for (int j = 0; j < TN; j++)
                    acc[i][j] = fmaf(a[i], b[j], acc[i][j]);
        }
        __syncthreads();
    }

    #pragma unroll
    for (int i = 0; i < TM; i++) {
        int gr = row0 + tm + i;
        if (gr < M) {
            #pragma unroll
            for (int j = 0; j < TN; j += 4) {
                float4 v = make_float4(acc[i][j], acc[i][j+1], acc[i][j+2], acc[i][j+3]);
                *reinterpret_cast<float4*>(C + (size_t)gr * BN + tn + j) = v;
            }
        }
    }
}

__global__ void __launch_bounds__(128)
k_gemm1(const float* __restrict__ x, const float* __restrict__ W1, int M) {
    gemm_dev<64, 128, 32, 8, 8>(x, W1, g_h1, M, FIN);
}

__global__ void __launch_bounds__(128)
k_gemm2(const float* __restrict__ W2, int M) {
    gemm_dev<128, 64, 32, 8, 8>(g_agg, W2, g_h2, M, HID);
}

// ---------------- gather aggregation (one warp per node, no atomics) --------
// layer 1: F=128, lane owns float4; epilogue adds self-loop + bias + relu
__global__ void k_agg1(const float* __restrict__ bias, int N) {
    int gw   = (blockIdx.x * blockDim.x + threadIdx.x) >> 5;
    int lane = threadIdx.x & 31;
    if (gw >= N) return;
    const int node  = gw;
    const int start = g_rowstart[node];
    const int end   = g_rowstart[node + 1];

    const float4* __restrict__ h4 = reinterpret_cast<const float4*>(g_h1);
    float4 acc = make_float4(0.f, 0.f, 0.f, 0.f);

    for (int base = start; base < end; base += 32) {
        int e = base + lane;
        int s = 0; float w = 0.f;
        if (e < end) { s = g_esrc[e]; w = g_ew[e]; }
        int cnt = min(32, end - base);
        for (int j = 0; j < cnt; j++) {
            int   sj = __shfl_sync(0xffffffffu, s, j);
            float wj = __shfl_sync(0xffffffffu, w, j);
            float4 hv = h4[(size_t)sj * 32 + lane];
            acc.x = fmaf(hv.x, wj, acc.x);
            acc.y = fmaf(hv.y, wj, acc.y);
            acc.z = fmaf(hv.z, wj, acc.z);
            acc.w = fmaf(hv.w, wj, acc.w);
        }
    }

    float di = g_dinv[node];
    float sw = di * di;
    float4 hs = h4[(size_t)node * 32 + lane];
    float4 bv = reinterpret_cast<const float4*>(bias)[lane];
    float4 r;
    r.x = fmaxf(fmaf(acc.x, di, fmaf(hs.x, sw, bv.x)), 0.f);
    r.y = fmaxf(fmaf(acc.y, di, fmaf(hs.y, sw, bv.y)), 0.f);
    r.z = fmaxf(fmaf(acc.z, di, fmaf(hs.z, sw, bv.z)), 0.f);
    r.w = fmaxf(fmaf(acc.w, di, fmaf(hs.w, sw, bv.w)), 0.f);
    reinterpret_cast<float4*>(g_agg)[(size_t)node * 32 + lane] = r;
}

// layer 2: F=64, lane owns float2; epilogue adds self-loop + bias (no relu)
__global__ void k_agg2(const float* __restrict__ bias, float* __restrict__ out, int N) {
    int gw   = (blockIdx.x * blockDim.x + threadIdx.x) >> 5;
    int lane = threadIdx.x & 31;
    if (gw >= N) return;
    const int node  = gw;
    const int start = g_rowstart[node];
    const int end   = g_rowstart[node + 1];

    const float2* __restrict__ h2 = reinterpret_cast<const float2*>(g_h2);
    float2 acc = make_float2(0.f, 0.f);

    for (int base = start; base < end; base += 32) {
        int e = base + lane;
        int s = 0; float w = 0.f;
        if (e < end) { s = g_esrc[e]; w = g_ew[e]; }
        int cnt = min(32, end - base);
        for (int j = 0; j < cnt; j++) {
            int   sj = __shfl_sync(0xffffffffu, s, j);
            float wj = __shfl_sync(0xffffffffu, w, j);
            float2 hv = h2[(size_t)sj * 32 + lane];
            acc.x = fmaf(hv.x, wj, acc.x);
            acc.y = fmaf(hv.y, wj, acc.y);
        }
    }

    float di = g_dinv[node];
    float sw = di * di;
    float2 hs = h2[(size_t)node * 32 + lane];
    float2 bv = reinterpret_cast<const float2*>(bias)[lane];
    float2 r;
    r.x = fmaf(acc.x, di, fmaf(hs.x, sw, bv.x));
    r.y = fmaf(acc.y, di, fmaf(hs.y, sw, bv.y));
    reinterpret_cast<float2*>(out)[(size_t)node * 32 + lane] = r;
}

// ---------------- launch ------------------------------------------------------
extern "C" void kernel_launch(void* const* d_in, const int* in_sizes, int n_in,
                              void* d_out, int out_size) {
    const float* x     = (const float*)d_in[0];
    const void*  edges = d_in[1];                 // edge_index [2, E], int32 or int64
    const float* W1    = (const float*)d_in[2];
    const float* b1    = (const float*)d_in[3];
    const float* W2    = (const float*)d_in[4];
    const float* b2    = (const float*)d_in[5];
    float*       out   = (float*)d_out;

    const int E = in_sizes[1] / 2;     // 800000
    const int N = in_sizes[0] / FIN;   // 50000

    const int nb256_N = (N + 255) / 256;
    const int nb256_E = (E + 255) / 256;

    // dtype probe + CSR build
    k_detect   <<<1, 1>>>(edges, N, E);
    k_deg_zero <<<nb256_N, 256>>>(N);
    k_deg_count<<<nb256_E, 256>>>(edges, E, N);
    k_dinv     <<<nb256_N, 256>>>(N);
    k_scan_part<<<nb256_N, 256>>>(N);
    k_scan_mid <<<1, 256>>>(nb256_N);
    k_scan_add <<<nb256_N, 256>>>(N, E);
    k_perm     <<<nb256_E, 256>>>(edges, E, N);

    // layer 1
    k_gemm1<<<(N + 63) / 64, 128>>>(x, W1, N);
    k_agg1 <<<(N * 32 + 255) / 256, 256>>>(b1, N);

    // layer 2
    k_gemm2<<<(N + 127) / 128, 128>>>(W2, N);
    k_agg2 <<<(N * 32 + 255) / 256, 256>>>(b2, out, N);
}

// round 4
// speedup vs baseline: 1.1195x; 1.1195x over previous
#include <cuda_runtime.h>
#include <cstdint>

// Problem-fixed sizes
#define MAX_N 50000
#define MAX_E 800000
#define FIN 128
#define HID 128
#define FOUT 64

// ---------------- scratch (device globals; no allocation allowed) -----------
__device__ __align__(16) float g_h1 [MAX_N * HID];   // x @ W1
__device__ __align__(16) float g_agg[MAX_N * HID];   // relu(aggregate(h1)) + b1
__device__ __align__(16) float g_h2 [MAX_N * FOUT];  // agg @ W2
__device__ float g_dinv[MAX_N];
__device__ int   g_deg [MAX_N];
__device__ int   g_rowstart[MAX_N + 1];
__device__ int   g_cursor[MAX_N];
__device__ int   g_esrc[MAX_E];
__device__ __align__(8) float g_ew[MAX_E];           // dinv[src] per sorted edge
__device__ int   g_bsum[256];
__device__ int   g_is64;                              // edge_index dtype flag

// ---------------- packed f32x2 helpers ---------------------------------------
__device__ __forceinline__ unsigned long long pack2(float lo, float hi) {
    unsigned long long r;
    asm("mov.b64 %0, {%1, %2};" : "=l"(r) : "f"(lo), "f"(hi));
    return r;
}
__device__ __forceinline__ void unpack2(unsigned long long v, float& lo, float& hi) {
    asm("mov.b64 {%0, %1}, %2;" : "=f"(lo), "=f"(hi) : "l"(v));
}
__device__ __forceinline__ void fma2(unsigned long long& d,
                                     unsigned long long a, unsigned long long b) {
    asm("fma.rn.f32x2 %0, %1, %2, %3;" : "=l"(d) : "l"(a), "l"(b), "l"(d));
}

// ---------------- edge dtype probe + degree zero (fused) ---------------------
// If the buffer really is int64, the first 32 values (as int64) are node ids in
// [0, N). If int32 data is misread as int64, values pack lo + hi*2^32 with hi a
// random node id -> out of range almost surely within 32 samples.
__global__ void k_deg_zero(const void* __restrict__ edges, int N, int E) {
    int i = blockIdx.x * blockDim.x + threadIdx.x;
    if (i < N) g_deg[i] = 0;
    if (blockIdx.x == 0 && threadIdx.x == 0) {
        const long long* p = (const long long*)edges;
        int ok64 = 1;
        int n = (E < 32) ? E : 32;
        for (int j = 0; j < n; j++) {
            long long v = p[j];
            if (v < 0 || v >= N) { ok64 = 0; break; }
        }
        g_is64 = ok64;
    }
}

__device__ __forceinline__ int edge_at(const void* edges, int is64, long long idx) {
    if (is64) return (int)((const long long*)edges)[idx];
    return ((const int*)edges)[idx];
}

// ---------------- degree / CSR build ----------------------------------------
__global__ void k_deg_count(const void* __restrict__ edges, int E, int N) {
    int e = blockIdx.x * blockDim.x + threadIdx.x;
    if (e < E) {
        int is64 = g_is64;                              // uniform load
        int d = edge_at(edges, is64, (long long)E + e); // dst row
        if ((unsigned)d < (unsigned)N) atomicAdd(&g_deg[d], 1);
    }
}

__global__ void k_dinv(int N) {
    int i = blockIdx.x * blockDim.x + threadIdx.x;
    if (i < N) g_dinv[i] = rsqrtf((float)(g_deg[i] + 1));   // +1 self loop
}

__global__ void k_scan_part(int N) {
    __shared__ int s[256];
    int t = threadIdx.x;
    int i = blockIdx.x * 256 + t;
    int v = (i < N) ? g_deg[i] : 0;
    s[t] = v;
    __syncthreads();
    #pragma unroll
    for (int off = 1; off < 256; off <<= 1) {
        int x = (t >= off) ? s[t - off] : 0;
        __syncthreads();
        s[t] += x;
        __syncthreads();
    }
    if (i < N) g_rowstart[i] = s[t] - v;   // exclusive within block
    if (t == 255) g_bsum[blockIdx.x] = s[255];
}

__global__ void k_scan_mid(int nb) {
    __shared__ int s[256];
    int t = threadIdx.x;
    int v = (t < nb) ? g_bsum[t] : 0;
    s[t] = v;
    __syncthreads();
    #pragma unroll
    for (int off = 1; off < 256; off <<= 1) {
        int x = (t >= off) ? s[t - off] : 0;
        __syncthreads();
        s[t] += x;
        __syncthreads();
    }
    if (t < nb) g_bsum[t] = s[t] - v;      // exclusive block offsets
}

__global__ void k_scan_add(int N, int E) {
    int i = blockIdx.x * 256 + threadIdx.x;
    if (i < N) {
        int r = g_rowstart[i] + g_bsum[blockIdx.x];
        g_rowstart[i] = r;
        g_cursor[i]   = r;
    }
    if (i == 0) g_rowstart[N] = E;
}

__global__ void k_perm(const void* __restrict__ edges, int E, int N) {
    int e = blockIdx.x * blockDim.x + threadIdx.x;
    if (e < E) {
        int is64 = g_is64;
        int s = edge_at(edges, is64, e);
        int d = edge_at(edges, is64, (long long)E + e);
        if ((unsigned)d < (unsigned)N && (unsigned)s < (unsigned)N) {
            int pos = atomicAdd(&g_cursor[d], 1);
            g_esrc[pos] = s;
            g_ew[pos]   = g_dinv[s];
        }
    }
}

// ---------------- f32x2 SIMT GEMM: C[M,BN] = A[M,Kd] @ W[Kd,BN] --------------
// Double-buffered shared tiles, register-staged global loads, A transposed in
// shared for vector LDS on the M axis. Inner product uses packed fma.rn.f32x2.
template<int BM, int BN, int BK, int THREADS>
__device__ __forceinline__ void gemm2x_dev(const float* __restrict__ A,
                                           const float* __restrict__ W,
                                           float* __restrict__ C,
                                           int M, int Kd) {
    constexpr int TM = 8, TN = 8;
    __shared__ float As[2][BK][BM + 4];
    __shared__ float Ws[2][BK][BN];

    const int tid = threadIdx.x;
    const int tx  = tid % (BN / TN);
    const int ty  = tid / (BN / TN);
    const int tm  = ty * TM;
    const int tn  = tx * TN;
    const int row0 = blockIdx.x * BM;

    constexpr int A_LD = (BM * BK / 4) / THREADS;   // float4 per thread (A)
    constexpr int W_LD = (BK * BN / 4) / THREADS;   // float4 per thread (W)

    unsigned long long acc[TM][TN / 2];
    #pragma unroll
    for (int i = 0; i < TM; i++)
        #pragma unroll
        for (int j = 0; j < TN / 2; j++) acc[i][j] = 0ull;

    float4 aReg[A_LD], wReg[W_LD];

    // ---- staging helpers ----
    auto ldg_tiles = [&](int kc) {
        #pragma unroll
        for (int t = 0; t < A_LD; t++) {
            int idx = tid + t * THREADS;
            int m   = idx / (BK / 4);
            int k4  = (idx % (BK / 4)) * 4;
            int gr  = row0 + m;
            aReg[t] = (gr < M)
                ? *reinterpret_cast<const float4*>(A + (size_t)gr * Kd + kc + k4)
                : make_float4(0.f, 0.f, 0.f, 0.f);
        }
        #pragma unroll
        for (int t = 0; t < W_LD; t++) {
            int idx = tid + t * THREADS;
            wReg[t] = reinterpret_cast<const float4*>(W + (size_t)kc * BN)[idx];
        }
    };
    auto sts_tiles = [&](int buf) {
        #pragma unroll
        for (int t = 0; t < A_LD; t++) {
            int idx = tid + t * THREADS;
            int m   = idx / (BK / 4);
            int k4  = (idx % (BK / 4)) * 4;
            As[buf][k4 + 0][m] = aReg[t].x;
            As[buf][k4 + 1][m] = aReg[t].y;
            As[buf][k4 + 2][m] = aReg[t].z;
            As[buf][k4 + 3][m] = aReg[t].w;
        }
        #pragma unroll
        for (int t = 0; t < W_LD; t++) {
            int idx = tid + t * THREADS;
            int wk  = idx / (BN / 4);
            int wn  = (idx % (BN / 4)) * 4;
            *reinterpret_cast<float4*>(&Ws[buf][wk][wn]) = wReg[t];
        }
    };

    ldg_tiles(0);
    sts_tiles(0);
    __syncthreads();

    const int T = Kd / BK;
    for (int t = 0; t < T; t++) {
        const int buf = t & 1;
        if (t + 1 < T) ldg_tiles((t + 1) * BK);

        #pragma unroll
        for (int k = 0; k < BK; k++) {
            float4 a0 = *reinterpret_cast<const float4*>(&As[buf][k][tm]);
            float4 a1 = *reinterpret_cast<const float4*>(&As[buf][k][tm + 4]);
            float4 b0 = *reinterpret_cast<const float4*>(&Ws[buf][k][tn]);
            float4 b1 = *reinterpret_cast<const float4*>(&Ws[buf][k][tn + 4]);
            unsigned long long pb[4] = {
                pack2(b0.x, b0.y), pack2(b0.z, b0.w),
                pack2(b1.x, b1.y), pack2(b1.z, b1.w)
            };
            float av[8] = {a0.x, a0.y, a0.z, a0.w, a1.x, a1.y, a1.z, a1.w};
            #pragma unroll
            for (int i = 0; i < TM; i++) {
                unsigned long long pa = pack2(av[i], av[i]);
                #pragma unroll
                for (int j = 0; j < TN / 2; j++) fma2(acc[i][j], pa, pb[j]);
            }
        }

        if (t + 1 < T) {
            sts_tiles(buf ^ 1);
            __syncthreads();
        }
    }

    // epilogue
    #pragma unroll
    for (int i = 0; i < TM; i++) {
        int gr = row0 + tm + i;
        if (gr < M) {
            float c[TN];
            #pragma unroll
            for (int j = 0; j < TN / 2; j++) unpack2(acc[i][j], c[2 * j], c[2 * j + 1]);
            *reinterpret_cast<float4*>(C + (size_t)gr * BN + tn) =
                make_float4(c[0], c[1], c[2], c[3]);
            *reinterpret_cast<float4*>(C + (size_t)gr * BN + tn + 4) =
                make_float4(c[4], c[5], c[6], c[7]);
        }
    }
}

__global__ void __launch_bounds__(256, 2)
k_gemm1(const float* __restrict__ x, const float* __restrict__ W1, int M) {
    gemm2x_dev<128, 128, 16, 256>(x, W1, g_h1, M, FIN);
}

__global__ void __launch_bounds__(128)
k_gemm2(const float* __restrict__ W2, int M) {
    gemm2x_dev<128, 64, 16, 128>(g_agg, W2, g_h2, M, HID);
}

// ---------------- gather aggregation (one warp per node, no atomics) --------
// layer 1: F=128, lane owns float4; epilogue adds self-loop + bias + relu
__global__ void k_agg1(const float* __restrict__ bias, int N) {
    int gw   = (blockIdx.x * blockDim.x + threadIdx.x) >> 5;
    int lane = threadIdx.x & 31;
    if (gw >= N) return;
    const int node  = gw;
    const int start = g_rowstart[node];
    const int end   = g_rowstart[node + 1];

    const float4* __restrict__ h4 = reinterpret_cast<const float4*>(g_h1);
    float4 acc = make_float4(0.f, 0.f, 0.f, 0.f);

    for (int base = start; base < end; base += 32) {
        int e = base + lane;
        int s = 0; float w = 0.f;
        if (e < end) { s = g_esrc[e]; w = g_ew[e]; }
        int cnt = min(32, end - base);
        for (int j = 0; j < cnt; j++) {
            int   sj = __shfl_sync(0xffffffffu, s, j);
            float wj = __shfl_sync(0xffffffffu, w, j);
            float4 hv = h4[(size_t)sj * 32 + lane];
            acc.x = fmaf(hv.x, wj, acc.x);
            acc.y = fmaf(hv.y, wj, acc.y);
            acc.z = fmaf(hv.z, wj, acc.z);
            acc.w = fmaf(hv.w, wj, acc.w);
        }
    }

    float di = g_dinv[node];
    float sw = di * di;
    float4 hs = h4[(size_t)node * 32 + lane];
    float4 bv = reinterpret_cast<const float4*>(bias)[lane];
    float4 r;
    r.x = fmaxf(fmaf(acc.x, di, fmaf(hs.x, sw, bv.x)), 0.f);
    r.y = fmaxf(fmaf(acc.y, di, fmaf(hs.y, sw, bv.y)), 0.f);
    r.z = fmaxf(fmaf(acc.z, di, fmaf(hs.z, sw, bv.z)), 0.f);
    r.w = fmaxf(fmaf(acc.w, di, fmaf(hs.w, sw, bv.w)), 0.f);
    reinterpret_cast<float4*>(g_agg)[(size_t)node * 32 + lane] = r;
}

// layer 2: F=64, lane owns float2; epilogue adds self-loop + bias (no relu)
__global__ void k_agg2(const float* __restrict__ bias, float* __restrict__ out, int N) {
    int gw   = (blockIdx.x * blockDim.x + threadIdx.x) >> 5;
    int lane = threadIdx.x & 31;
    if (gw >= N) return;
    const int node  = gw;
    const int start = g_rowstart[node];
    const int end   = g_rowstart[node + 1];

    const float2* __restrict__ h2 = reinterpret_cast<const float2*>(g_h2);
    float2 acc = make_float2(0.f, 0.f);

    for (int base = start; base < end; base += 32) {
        int e = base + lane;
        int s = 0; float w = 0.f;
        if (e < end) { s = g_esrc[e]; w = g_ew[e]; }
        int cnt = min(32, end - base);
        for (int j = 0; j < cnt; j++) {
            int   sj = __shfl_sync(0xffffffffu, s, j);
            float wj = __shfl_sync(0xffffffffu, w, j);
            float2 hv = h2[(size_t)sj * 32 + lane];
            acc.x = fmaf(hv.x, wj, acc.x);
            acc.y = fmaf(hv.y, wj, acc.y);
        }
    }

    float di = g_dinv[node];
    float sw = di * di;
    float2 hs = h2[(size_t)node * 32 + lane];
    float2 bv = reinterpret_cast<const float2*>(bias)[lane];
    float2 r;
    r.x = fmaf(acc.x, di, fmaf(hs.x, sw, bv.x));
    r.y = fmaf(acc.y, di, fmaf(hs.y, sw, bv.y));
    reinterpret_cast<float2*>(out)[(size_t)node * 32 + lane] = r;
}

// ---------------- launch ------------------------------------------------------
extern "C" void kernel_launch(void* const* d_in, const int* in_sizes, int n_in,
                              void* d_out, int out_size) {
    const float* x     = (const float*)d_in[0];
    const void*  edges = d_in[1];                 // edge_index [2, E], int32 or int64
    const float* W1    = (const float*)d_in[2];
    const float* b1    = (const float*)d_in[3];
    const float* W2    = (const float*)d_in[4];
    const float* b2    = (const float*)d_in[5];
    float*       out   = (float*)d_out;

    const int E = in_sizes[1] / 2;     // 800000
    const int N = in_sizes[0] / FIN;   // 50000

    const int nb256_N = (N + 255) / 256;
    const int nb256_E = (E + 255) / 256;

    // dtype probe (fused) + CSR build
    k_deg_zero <<<nb256_N, 256>>>(edges, N, E);
    k_deg_count<<<nb256_E, 256>>>(edges, E, N);
    k_dinv     <<<nb256_N, 256>>>(N);
    k_scan_part<<<nb256_N, 256>>>(N);
    k_scan_mid <<<1, 256>>>(nb256_N);
    k_scan_add <<<nb256_N, 256>>>(N, E);
    k_perm     <<<nb256_E, 256>>>(edges, E, N);

    // layer 1
    k_gemm1<<<(N + 127) / 128, 256>>>(x, W1, N);
    k_agg1 <<<(N * 32 + 255) / 256, 256>>>(b1, N);

    // layer 2
    k_gemm2<<<(N + 127) / 128, 128>>>(W2, N);
    k_agg2 <<<(N * 32 + 255) / 256, 256>>>(b2, out, N);
}

// round 5
// speedup vs baseline: 1.1716x; 1.0465x over previous
#include <cuda_runtime.h>
#include <cstdint>

// Problem-fixed sizes
#define MAX_N 50000
#define MAX_E 800000
#define FIN 128
#define HID 128
#define FOUT 64

// ---------------- scratch (device globals; no allocation allowed) -----------
__device__ __align__(16) float g_h1 [MAX_N * HID];   // x @ W1
__device__ __align__(16) float g_agg[MAX_N * HID];   // relu(aggregate(h1)) + b1
__device__ __align__(16) float g_h2 [MAX_N * FOUT];  // agg @ W2
__device__ float g_dinv[MAX_N];
__device__ int   g_deg [MAX_N];
__device__ int   g_rowstart[MAX_N + 1];
__device__ int   g_cursor[MAX_N];
__device__ __align__(8) int2 g_epair[MAX_E];         // {src, dinv[src] bits}
__device__ int   g_bsum[256];
__device__ int   g_is64;                              // edge_index dtype flag

// ---------------- packed f32x2 helpers ---------------------------------------
__device__ __forceinline__ unsigned long long pack2(float lo, float hi) {
    unsigned long long r;
    asm("mov.b64 %0, {%1, %2};" : "=l"(r) : "f"(lo), "f"(hi));
    return r;
}
__device__ __forceinline__ void unpack2(unsigned long long v, float& lo, float& hi) {
    asm("mov.b64 {%0, %1}, %2;" : "=f"(lo), "=f"(hi) : "l"(v));
}
__device__ __forceinline__ void fma2(unsigned long long& d,
                                     unsigned long long a, unsigned long long b) {
    asm("fma.rn.f32x2 %0, %1, %2, %3;" : "=l"(d) : "l"(a), "l"(b), "l"(d));
}

// ---------------- edge dtype probe + degree zero (fused) ---------------------
__global__ void k_deg_zero(const void* __restrict__ edges, int N, int E) {
    int i = blockIdx.x * blockDim.x + threadIdx.x;
    if (i < N) g_deg[i] = 0;
    if (blockIdx.x == 0 && threadIdx.x == 0) {
        const long long* p = (const long long*)edges;
        int ok64 = 1;
        int n = (E < 32) ? E : 32;
        for (int j = 0; j < n; j++) {
            long long v = p[j];
            if (v < 0 || v >= N) { ok64 = 0; break; }
        }
        g_is64 = ok64;
    }
}

__device__ __forceinline__ int edge_at(const void* edges, int is64, long long idx) {
    if (is64) return (int)((const long long*)edges)[idx];
    return ((const int*)edges)[idx];
}

// ---------------- degree / CSR build ----------------------------------------
__global__ void k_deg_count(const void* __restrict__ edges, int E, int N) {
    int e = blockIdx.x * blockDim.x + threadIdx.x;
    if (e < E) {
        int is64 = g_is64;                              // uniform load
        int d = edge_at(edges, is64, (long long)E + e); // dst row
        if ((unsigned)d < (unsigned)N) atomicAdd(&g_deg[d], 1);
    }
}

// scan over degrees; also computes dinv (deg value already in hand)
__global__ void k_scan_part(int N) {
    __shared__ int s[256];
    int t = threadIdx.x;
    int i = blockIdx.x * 256 + t;
    int v = (i < N) ? g_deg[i] : 0;
    if (i < N) g_dinv[i] = rsqrtf((float)(v + 1));   // +1 self loop
    s[t] = v;
    __syncthreads();
    #pragma unroll
    for (int off = 1; off < 256; off <<= 1) {
        int x = (t >= off) ? s[t - off] : 0;
        __syncthreads();
        s[t] += x;
        __syncthreads();
    }
    if (i < N) g_rowstart[i] = s[t] - v;   // exclusive within block
    if (t == 255) g_bsum[blockIdx.x] = s[255];
}

__global__ void k_scan_mid(int nb) {
    __shared__ int s[256];
    int t = threadIdx.x;
    int v = (t < nb) ? g_bsum[t] : 0;
    s[t] = v;
    __syncthreads();
    #pragma unroll
    for (int off = 1; off < 256; off <<= 1) {
        int x = (t >= off) ? s[t - off] : 0;
        __syncthreads();
        s[t] += x;
        __syncthreads();
    }
    if (t < nb) g_bsum[t] = s[t] - v;      // exclusive block offsets
}

__global__ void k_scan_add(int N, int E) {
    int i = blockIdx.x * 256 + threadIdx.x;
    if (i < N) {
        int r = g_rowstart[i] + g_bsum[blockIdx.x];
        g_rowstart[i] = r;
        g_cursor[i]   = r;
    }
    if (i == 0) g_rowstart[N] = E;
}

__global__ void k_perm(const void* __restrict__ edges, int E, int N) {
    int e = blockIdx.x * blockDim.x + threadIdx.x;
    if (e < E) {
        int is64 = g_is64;
        int s = edge_at(edges, is64, e);
        int d = edge_at(edges, is64, (long long)E + e);
        if ((unsigned)d < (unsigned)N && (unsigned)s < (unsigned)N) {
            int pos = atomicAdd(&g_cursor[d], 1);
            g_epair[pos] = make_int2(s, __float_as_int(g_dinv[s]));  // one 8B store
        }
    }
}

// ---------------- f32x2 SIMT GEMM: C[M,BN] = A[M,Kd] @ W[Kd,BN] --------------
// Double-buffered shared tiles, register-staged global loads, A transposed in
// shared. B operand pairs are read straight from shared as 64-bit words (no
// packing); only the A broadcast needs a pack.
template<int BM, int BN, int BK, int THREADS>
__device__ __forceinline__ void gemm2x_dev(const float* __restrict__ A,
                                           const float* __restrict__ W,
                                           float* __restrict__ C,
                                           int M, int Kd) {
    constexpr int TM = 8, TN = 8;
    __shared__ float As[2][BK][BM + 4];
    __shared__ __align__(16) float Ws[2][BK][BN];

    const int tid = threadIdx.x;
    const int tx  = tid % (BN / TN);
    const int ty  = tid / (BN / TN);
    const int tm  = ty * TM;
    const int tn  = tx * TN;
    const int row0 = blockIdx.x * BM;

    constexpr int A_LD = (BM * BK / 4) / THREADS;
    constexpr int W_LD = (BK * BN / 4) / THREADS;

    unsigned long long acc[TM][TN / 2];
    #pragma unroll
    for (int i = 0; i < TM; i++)
        #pragma unroll
        for (int j = 0; j < TN / 2; j++) acc[i][j] = 0ull;

    float4 aReg[A_LD], wReg[W_LD];

    auto ldg_tiles = [&](int kc) {
        #pragma unroll
        for (int t = 0; t < A_LD; t++) {
            int idx = tid + t * THREADS;
            int m   = idx / (BK / 4);
            int k4  = (idx % (BK / 4)) * 4;
            int gr  = row0 + m;
            aReg[t] = (gr < M)
                ? *reinterpret_cast<const float4*>(A + (size_t)gr * Kd + kc + k4)
                : make_float4(0.f, 0.f, 0.f, 0.f);
        }
        #pragma unroll
        for (int t = 0; t < W_LD; t++) {
            int idx = tid + t * THREADS;
            wReg[t] = reinterpret_cast<const float4*>(W + (size_t)kc * BN)[idx];
        }
    };
    auto sts_tiles = [&](int buf) {
        #pragma unroll
        for (int t = 0; t < A_LD; t++) {
            int idx = tid + t * THREADS;
            int m   = idx / (BK / 4);
            int k4  = (idx % (BK / 4)) * 4;
            As[buf][k4 + 0][m] = aReg[t].x;
            As[buf][k4 + 1][m] = aReg[t].y;
            As[buf][k4 + 2][m] = aReg[t].z;
            As[buf][k4 + 3][m] = aReg[t].w;
        }
        #pragma unroll
        for (int t = 0; t < W_LD; t++) {
            int idx = tid + t * THREADS;
            int wk  = idx / (BN / 4);
            int wn  = (idx % (BN / 4)) * 4;
            *reinterpret_cast<float4*>(&Ws[buf][wk][wn]) = wReg[t];
        }
    };

    ldg_tiles(0);
    sts_tiles(0);
    __syncthreads();

    const int T = Kd / BK;
    for (int t = 0; t < T; t++) {
        const int buf = t & 1;
        if (t + 1 < T) ldg_tiles((t + 1) * BK);

        #pragma unroll
        for (int k = 0; k < BK; k++) {
            float4 a0 = *reinterpret_cast<const float4*>(&As[buf][k][tm]);
            float4 a1 = *reinterpret_cast<const float4*>(&As[buf][k][tm + 4]);
            const unsigned long long* bw =
                reinterpret_cast<const unsigned long long*>(&Ws[buf][k][tn]);
            unsigned long long pb0 = bw[0], pb1 = bw[1], pb2 = bw[2], pb3 = bw[3];
            float av[8] = {a0.x, a0.y, a0.z, a0.w, a1.x, a1.y, a1.z, a1.w};
            #pragma unroll
            for (int i = 0; i < TM; i++) {
                unsigned long long pa = pack2(av[i], av[i]);
                fma2(acc[i][0], pa, pb0);
                fma2(acc[i][1], pa, pb1);
                fma2(acc[i][2], pa, pb2);
                fma2(acc[i][3], pa, pb3);
            }
        }

        if (t + 1 < T) {
            sts_tiles(buf ^ 1);
            __syncthreads();
        }
    }

    #pragma unroll
    for (int i = 0; i < TM; i++) {
        int gr = row0 + tm + i;
        if (gr < M) {
            float c[TN];
            #pragma unroll
            for (int j = 0; j < TN / 2; j++) unpack2(acc[i][j], c[2 * j], c[2 * j + 1]);
            *reinterpret_cast<float4*>(C + (size_t)gr * BN + tn) =
                make_float4(c[0], c[1], c[2], c[3]);
            *reinterpret_cast<float4*>(C + (size_t)gr * BN + tn + 4) =
                make_float4(c[4], c[5], c[6], c[7]);
        }
    }
}

__global__ void __launch_bounds__(256, 2)
k_gemm1(const float* __restrict__ x, const float* __restrict__ W1, int M) {
    gemm2x_dev<128, 128, 16, 256>(x, W1, g_h1, M, FIN);
}

__global__ void __launch_bounds__(128)
k_gemm2(const float* __restrict__ W2, int M) {
    gemm2x_dev<128, 64, 16, 128>(g_agg, W2, g_h2, M, HID);
}

// ---------------- gather aggregation (one warp per node, no atomics) --------
// Edge pairs are read with a warp-uniform LDG (L1 broadcast) — no shfl staging.
// layer 1: F=128, lane owns float4; epilogue adds self-loop + bias + relu
__global__ void k_agg1(const float* __restrict__ bias, int N) {
    int gw   = (blockIdx.x * blockDim.x + threadIdx.x) >> 5;
    int lane = threadIdx.x & 31;
    if (gw >= N) return;
    const int node  = gw;
    const int start = g_rowstart[node];
    const int end   = g_rowstart[node + 1];

    const float4* __restrict__ h4 = reinterpret_cast<const float4*>(g_h1);
    float4 acc = make_float4(0.f, 0.f, 0.f, 0.f);

    #pragma unroll 4
    for (int e = start; e < end; e++) {
        int2  pr = g_epair[e];                 // uniform across warp
        float w  = __int_as_float(pr.y);
        float4 hv = h4[(size_t)pr.x * 32 + lane];
        acc.x = fmaf(hv.x, w, acc.x);
        acc.y = fmaf(hv.y, w, acc.y);
        acc.z = fmaf(hv.z, w, acc.z);
        acc.w = fmaf(hv.w, w, acc.w);
    }

    float di = g_dinv[node];
    float sw = di * di;
    float4 hs = h4[(size_t)node * 32 + lane];
    float4 bv = reinterpret_cast<const float4*>(bias)[lane];
    float4 r;
    r.x = fmaxf(fmaf(acc.x, di, fmaf(hs.x, sw, bv.x)), 0.f);
    r.y = fmaxf(fmaf(acc.y, di, fmaf(hs.y, sw, bv.y)), 0.f);
    r.z = fmaxf(fmaf(acc.z, di, fmaf(hs.z, sw, bv.z)), 0.f);
    r.w = fmaxf(fmaf(acc.w, di, fmaf(hs.w, sw, bv.w)), 0.f);
    reinterpret_cast<float4*>(g_agg)[(size_t)node * 32 + lane] = r;
}

// layer 2: F=64, lane owns float2; epilogue adds self-loop + bias (no relu)
__global__ void k_agg2(const float* __restrict__ bias, float* __restrict__ out, int N) {
    int gw   = (blockIdx.x * blockDim.x + threadIdx.x) >> 5;
    int lane = threadIdx.x & 31;
    if (gw >= N) return;
    const int node  = gw;
    const int start = g_rowstart[node];
    const int end   = g_rowstart[node + 1];

    const float2* __restrict__ h2 = reinterpret_cast<const float2*>(g_h2);
    float2 acc = make_float2(0.f, 0.f);

    #pragma unroll 4
    for (int e = start; e < end; e++) {
        int2  pr = g_epair[e];                 // uniform across warp
        float w  = __int_as_float(pr.y);
        float2 hv = h2[(size_t)pr.x * 32 + lane];
        acc.x = fmaf(hv.x, w, acc.x);
        acc.y = fmaf(hv.y, w, acc.y);
    }

    float di = g_dinv[node];
    float sw = di * di;
    float2 hs = h2[(size_t)node * 32 + lane];
    float2 bv = reinterpret_cast<const float2*>(bias)[lane];
    float2 r;
    r.x = fmaf(acc.x, di, fmaf(hs.x, sw, bv.x));
    r.y = fmaf(acc.y, di, fmaf(hs.y, sw, bv.y));
    reinterpret_cast<float2*>(out)[(size_t)node * 32 + lane] = r;
}

// ---------------- launch ------------------------------------------------------
extern "C" void kernel_launch(void* const* d_in, const int* in_sizes, int n_in,
                              void* d_out, int out_size) {
    const float* x     = (const float*)d_in[0];
    const void*  edges = d_in[1];                 // edge_index [2, E], int32 or int64
    const float* W1    = (const float*)d_in[2];
    const float* b1    = (const float*)d_in[3];
    const float* W2    = (const float*)d_in[4];
    const float* b2    = (const float*)d_in[5];
    float*       out   = (float*)d_out;

    const int E = in_sizes[1] / 2;     // 800000
    const int N = in_sizes[0] / FIN;   // 50000

    const int nb256_N = (N + 255) / 256;
    const int nb256_E = (E + 255) / 256;

    // dtype probe (fused) + CSR build
    k_deg_zero <<<nb256_N, 256>>>(edges, N, E);
    k_deg_count<<<nb256_E, 256>>>(edges, E, N);
    k_scan_part<<<nb256_N, 256>>>(N);
    k_scan_mid <<<1, 256>>>(nb256_N);
    k_scan_add <<<nb256_N, 256>>>(N, E);
    k_perm     <<<nb256_E, 256>>>(edges, E, N);

    // layer 1
    k_gemm1<<<(N + 127) / 128, 256>>>(x, W1, N);
    k_agg1 <<<(N * 32 + 255) / 256, 256>>>(b1, N);

    // layer 2
    k_gemm2<<<(N + 127) / 128, 128>>>(W2, N);
    k_agg2 <<<(N * 32 + 255) / 256, 256>>>(b2, out, N);
}

// round 7
// speedup vs baseline: 1.2895x; 1.1007x over previous
#include <cuda_runtime.h>
#include <cuda_fp16.h>
#include <cstdint>

// Problem-fixed sizes
#define MAX_N 50000
#define MAX_E 800000
#define FIN 128
#define HID 128
#define FOUT 64
#define SCAN_TILE 2048   // 256 threads * 8 elements

// ---------------- scratch (device globals; no allocation allowed) -----------
__device__ __align__(16) __half g_h1h[MAX_N * HID];   // x @ W1   (fp16 storage)
__device__ __align__(16) float  g_agg [MAX_N * HID];  // relu(agg(h1)) + b1 (fp32)
__device__ __align__(16) __half g_h2h[MAX_N * FOUT];  // agg @ W2 (fp16 storage)
__device__ float g_dinv[MAX_N];
__device__ __align__(16) int g_deg[MAX_N];            // zero-init; re-zeroed each pass
__device__ int   g_rowstart[MAX_N + 1];
__device__ int   g_cursor[MAX_N];
__device__ __align__(8) int2 g_epair[MAX_E];          // {src, dinv[src] bits}
__device__ int   g_tilesum[64];                       // per-tile degree sums
__device__ int   g_is64;                              // edge_index dtype flag

// ---------------- packed f32x2 helpers ---------------------------------------
__device__ __forceinline__ unsigned long long pack2(float lo, float hi) {
    unsigned long long r;
    asm("mov.b64 %0, {%1, %2};" : "=l"(r) : "f"(lo), "f"(hi));
    return r;
}
__device__ __forceinline__ void unpack2(unsigned long long v, float& lo, float& hi) {
    asm("mov.b64 {%0, %1}, %2;" : "=f"(lo), "=f"(hi) : "l"(v));
}
__device__ __forceinline__ void fma2(unsigned long long& d,
                                     unsigned long long a, unsigned long long b) {
    asm("fma.rn.f32x2 %0, %1, %2, %3;" : "=l"(d) : "l"(a), "l"(b), "l"(d));
}

__device__ __forceinline__ int edge_at(const void* edges, int is64, long long idx) {
    if (is64) return (int)((const long long*)edges)[idx];
    return ((const int*)edges)[idx];
}

// ---------------- degree count (+ dtype probe) -------------------------------
__global__ void k_deg_count(const void* __restrict__ edges, int E, int N) {
    __shared__ int sh_is64;
    // warp 0: dtype probe (int32 misread as int64 -> out of [0,N) almost surely)
    if (threadIdx.x < 32) {
        int n = (E < 32) ? E : 32;
        int ok = 1;
        if ((int)threadIdx.x < n) {
            long long v = ((const long long*)edges)[threadIdx.x];
            ok = (v >= 0 && v < N);
        }
        unsigned mask = __ballot_sync(0xffffffffu, ok);
        if (threadIdx.x == 0) {
            sh_is64 = (mask == 0xffffffffu);
            if (blockIdx.x == 0) g_is64 = sh_is64;
        }
    }
    __syncthreads();
    int is64 = sh_is64;

    int e = blockIdx.x * blockDim.x + threadIdx.x;
    if (e < E) {
        int d = edge_at(edges, is64, (long long)E + e);
        if ((unsigned)d < (unsigned)N) atomicAdd(&g_deg[d], 1);
    }
}

// ---------------- spin-free two-kernel scan ----------------------------------
// k_scan_a: per-tile degree sums (plain stores; kernel boundary orders them).
__global__ void k_scan_a(int N) {
    __shared__ int s[256];
    const int t = threadIdx.x;
    const int b = blockIdx.x;
    const int base = b * SCAN_TILE + t * 8;

    int sum = 0;
    if (base + 7 < N) {
        int4 p0 = *reinterpret_cast<const int4*>(&g_deg[base]);
        int4 p1 = *reinterpret_cast<const int4*>(&g_deg[base + 4]);
        sum = p0.x + p0.y + p0.z + p0.w + p1.x + p1.y + p1.z + p1.w;
    } else {
        #pragma unroll
        for (int j = 0; j < 8; j++) {
            int i = base + j;
            if (i < N) sum += g_deg[i];
        }
    }
    s[t] = sum;
    __syncthreads();
    #pragma unroll
    for (int off = 128; off; off >>= 1) {
        if (t < off) s[t] += s[t + off];
        __syncthreads();
    }
    if (t == 0) g_tilesum[b] = s[0];
}

// k_scan_b: dinv + exclusive scan (rowstart/cursor) + deg re-zero. Global
// offset = sum of predecessor tile sums (deterministic, no waiting).
__global__ void k_scan_b(int N, int E) {
    __shared__ int s[256];
    __shared__ int s_prefix;
    const int t = threadIdx.x;
    const int b = blockIdx.x;
    const int base = b * SCAN_TILE + t * 8;

    int v[8];
    int sum = 0;
    if (base + 7 < N) {
        int4 p0 = *reinterpret_cast<const int4*>(&g_deg[base]);
        int4 p1 = *reinterpret_cast<const int4*>(&g_deg[base + 4]);
        v[0]=p0.x; v[1]=p0.y; v[2]=p0.z; v[3]=p0.w;
        v[4]=p1.x; v[5]=p1.y; v[6]=p1.z; v[7]=p1.w;
        *reinterpret_cast<int4*>(&g_deg[base])     = make_int4(0,0,0,0);
        *reinterpret_cast<int4*>(&g_deg[base + 4]) = make_int4(0,0,0,0);
        #pragma unroll
        for (int j = 0; j < 8; j++) {
            g_dinv[base + j] = rsqrtf((float)(v[j] + 1));  // +1 self loop
            sum += v[j];
        }
    } else {
        #pragma unroll
        for (int j = 0; j < 8; j++) {
            int i = base + j;
            int d = (i < N) ? g_deg[i] : 0;
            v[j] = d;
            if (i < N) { g_deg[i] = 0; g_dinv[i] = rsqrtf((float)(d + 1)); }
            sum += d;
        }
    }

    s[t] = sum;
    __syncthreads();
    #pragma unroll
    for (int off = 1; off < 256; off <<= 1) {
        int x = (t >= off) ? s[t - off] : 0;
        __syncthreads();
        s[t] += x;
        __syncthreads();
    }
    const int thr_excl = s[t] - sum;

    if (t < 32) {
        int prefix = 0;
        for (int p = t; p < b; p += 32) prefix += g_tilesum[p];
        #pragma unroll
        for (int off = 16; off; off >>= 1)
            prefix += __shfl_xor_sync(0xffffffffu, prefix, off);
        if (t == 0) s_prefix = prefix;
    }
    __syncthreads();

    int pos = s_prefix + thr_excl;
    #pragma unroll
    for (int j = 0; j < 8; j++) {
        int i = base + j;
        if (i < N) { g_rowstart[i] = pos; g_cursor[i] = pos; }
        pos += v[j];
    }
    if (b == 0 && t == 0) g_rowstart[N] = E;
}

__global__ void k_perm(const void* __restrict__ edges, int E, int N) {
    int e = blockIdx.x * blockDim.x + threadIdx.x;
    if (e < E) {
        int is64 = g_is64;
        int s = edge_at(edges, is64, e);
        int d = edge_at(edges, is64, (long long)E + e);
        if ((unsigned)d < (unsigned)N && (unsigned)s < (unsigned)N) {
            int pos = atomicAdd(&g_cursor[d], 1);
            g_epair[pos] = make_int2(s, __float_as_int(g_dinv[s]));
        }
    }
}

// ---------------- f32x2 SIMT GEMM, fp16 output -------------------------------
// C_half[M,BN] = A[M,Kd] @ W[Kd,BN]; fp32 accumulate, fp16 store.
template<int BM, int BN, int BK, int THREADS>
__device__ __forceinline__ void gemm2x_dev(const float* __restrict__ A,
                                           const float* __restrict__ W,
                                           __half* __restrict__ C,
                                           int M, int Kd) {
    constexpr int TM = 8, TN = 8;
    __shared__ float As[2][BK][BM + 4];
    __shared__ __align__(16) float Ws[2][BK][BN];

    const int tid = threadIdx.x;
    const int tx  = tid % (BN / TN);
    const int ty  = tid / (BN / TN);
    const int tm  = ty * TM;
    const int tn  = tx * TN;
    const int row0 = blockIdx.x * BM;

    constexpr int A_LD = (BM * BK / 4) / THREADS;
    constexpr int W_LD = (BK * BN / 4) / THREADS;

    unsigned long long acc[TM][TN / 2];
    #pragma unroll
    for (int i = 0; i < TM; i++)
        #pragma unroll
        for (int j = 0; j < TN / 2; j++) acc[i][j] = 0ull;

    float4 aReg[A_LD], wReg[W_LD];

    auto ldg_tiles = [&](int kc) {
        #pragma unroll
        for (int t = 0; t < A_LD; t++) {
            int idx = tid + t * THREADS;
            int m   = idx / (BK / 4);
            int k4  = (idx % (BK / 4)) * 4;
            int gr  = row0 + m;
            aReg[t] = (gr < M)
                ? *reinterpret_cast<const float4*>(A + (size_t)gr * Kd + kc + k4)
                : make_float4(0.f, 0.f, 0.f, 0.f);
        }
        #pragma unroll
        for (int t = 0; t < W_LD; t++) {
            int idx = tid + t * THREADS;
            wReg[t] = reinterpret_cast<const float4*>(W + (size_t)kc * BN)[idx];
        }
    };
    auto sts_tiles = [&](int buf) {
        #pragma unroll
        for (int t = 0; t < A_LD; t++) {
            int idx = tid + t * THREADS;
            int m   = idx / (BK / 4);
            int k4  = (idx % (BK / 4)) * 4;
            As[buf][k4 + 0][m] = aReg[t].x;
            As[buf][k4 + 1][m] = aReg[t].y;
            As[buf][k4 + 2][m] = aReg[t].z;
            As[buf][k4 + 3][m] = aReg[t].w;
        }
        #pragma unroll
        for (int t = 0; t < W_LD; t++) {
            int idx = tid + t * THREADS;
            int wk  = idx / (BN / 4);
            int wn  = (idx % (BN / 4)) * 4;
            *reinterpret_cast<float4*>(&Ws[buf][wk][wn]) = wReg[t];
        }
    };

    ldg_tiles(0);
    sts_tiles(0);
    __syncthreads();

    const int T = Kd / BK;
    for (int t = 0; t < T; t++) {
        const int buf = t & 1;
        if (t + 1 < T) ldg_tiles((t + 1) * BK);

        #pragma unroll
        for (int k = 0; k < BK; k++) {
            float4 a0 = *reinterpret_cast<const float4*>(&As[buf][k][tm]);
            float4 a1 = *reinterpret_cast<const float4*>(&As[buf][k][tm + 4]);
            const unsigned long long* bw =
                reinterpret_cast<const unsigned long long*>(&Ws[buf][k][tn]);
            unsigned long long pb0 = bw[0], pb1 = bw[1], pb2 = bw[2], pb3 = bw[3];
            float av[8] = {a0.x, a0.y, a0.z, a0.w, a1.x, a1.y, a1.z, a1.w};
            #pragma unroll
            for (int i = 0; i < TM; i++) {
                unsigned long long pa = pack2(av[i], av[i]);
                fma2(acc[i][0], pa, pb0);
                fma2(acc[i][1], pa, pb1);
                fma2(acc[i][2], pa, pb2);
                fma2(acc[i][3], pa, pb3);
            }
        }

        if (t + 1 < T) {
            sts_tiles(buf ^ 1);
            __syncthreads();
        }
    }

    #pragma unroll
    for (int i = 0; i < TM; i++) {
        int gr = row0 + tm + i;
        if (gr < M) {
            float c[TN];
            #pragma unroll
            for (int j = 0; j < TN / 2; j++) unpack2(acc[i][j], c[2 * j], c[2 * j + 1]);
            __half2 h0 = __floats2half2_rn(c[0], c[1]);
            __half2 h1 = __floats2half2_rn(c[2], c[3]);
            __half2 h2 = __floats2half2_rn(c[4], c[5]);
            __half2 h3 = __floats2half2_rn(c[6], c[7]);
            uint4 u = make_uint4(*reinterpret_cast<unsigned*>(&h0),
                                 *reinterpret_cast<unsigned*>(&h1),
                                 *reinterpret_cast<unsigned*>(&h2),
                                 *reinterpret_cast<unsigned*>(&h3));
            *reinterpret_cast<uint4*>(C + (size_t)gr * BN + tn) = u;
        }
    }
}

__global__ void __launch_bounds__(256, 2)
k_gemm1(const float* __restrict__ x, const float* __restrict__ W1, int M) {
    gemm2x_dev<128, 128, 16, 256>(x, W1, g_h1h, M, FIN);
}

__global__ void __launch_bounds__(128)
k_gemm2(const float* __restrict__ W2, int M) {
    gemm2x_dev<128, 64, 16, 128>(g_agg, W2, g_h2h, M, HID);
}

// ---------------- gather aggregation (one warp per node, no atomics) --------
// fp16 rows gathered, fp32 accumulation. Edge pairs via warp-uniform LDG.
// layer 1: F=128 halves, lane owns 4 halves (uint2); self-loop + bias + relu.
__global__ void k_agg1(const float* __restrict__ bias, int N) {
    int gw   = (blockIdx.x * blockDim.x + threadIdx.x) >> 5;
    int lane = threadIdx.x & 31;
    if (gw >= N) return;
    const int start = g_rowstart[gw];
    const int end   = g_rowstart[gw + 1];

    const uint2* __restrict__ hp = reinterpret_cast<const uint2*>(g_h1h);
    float4 acc = make_float4(0.f, 0.f, 0.f, 0.f);

    #pragma unroll 4
    for (int e = start; e < end; e++) {
        int2  pr = g_epair[e];                 // uniform across warp
        float w  = __int_as_float(pr.y);
        uint2 rv = hp[(size_t)pr.x * 32 + lane];
        float2 f0 = __half22float2(*reinterpret_cast<__half2*>(&rv.x));
        float2 f1 = __half22float2(*reinterpret_cast<__half2*>(&rv.y));
        acc.x = fmaf(f0.x, w, acc.x);
        acc.y = fmaf(f0.y, w, acc.y);
        acc.z = fmaf(f1.x, w, acc.z);
        acc.w = fmaf(f1.y, w, acc.w);
    }

    float di = g_dinv[gw];
    float sw = di * di;
    uint2 rs = hp[(size_t)gw * 32 + lane];
    float2 s0 = __half22float2(*reinterpret_cast<__half2*>(&rs.x));
    float2 s1 = __half22float2(*reinterpret_cast<__half2*>(&rs.y));
    float4 bv = reinterpret_cast<const float4*>(bias)[lane];
    float4 r;
    r.x = fmaxf(fmaf(acc.x, di, fmaf(s0.x, sw, bv.x)), 0.f);
    r.y = fmaxf(fmaf(acc.y, di, fmaf(s0.y, sw, bv.y)), 0.f);
    r.z = fmaxf(fmaf(acc.z, di, fmaf(s1.x, sw, bv.z)), 0.f);
    r.w = fmaxf(fmaf(acc.w, di, fmaf(s1.y, sw, bv.w)), 0.f);
    reinterpret_cast<float4*>(g_agg)[(size_t)gw * 32 + lane] = r;
}

// layer 2: F=64 halves, lane owns half2; self-loop + bias (no relu), fp32 out.
__global__ void k_agg2(const float* __restrict__ bias, float* __restrict__ out, int N) {
    int gw   = (blockIdx.x * blockDim.x + threadIdx.x) >> 5;
    int lane = threadIdx.x & 31;
    if (gw >= N) return;
    const int start = g_rowstart[gw];
    const int end   = g_rowstart[gw + 1];

    const __half2* __restrict__ hp = reinterpret_cast<const __half2*>(g_h2h);
    float2 acc = make_float2(0.f, 0.f);

    #pragma unroll 4
    for (int e = start; e < end; e++) {
        int2  pr = g_epair[e];                 // uniform across warp
        float w  = __int_as_float(pr.y);
        float2 f = __half22float2(hp[(size_t)pr.x * 32 + lane]);
        acc.x = fmaf(f.x, w, acc.x);
        acc.y = fmaf(f.y, w, acc.y);
    }

    float di = g_dinv[gw];
    float sw = di * di;
    float2 fs = __half22float2(hp[(size_t)gw * 32 + lane]);
    float2 bv = reinterpret_cast<const float2*>(bias)[lane];
    float2 r;
    r.x = fmaf(acc.x, di, fmaf(fs.x, sw, bv.x));
    r.y = fmaf(acc.y, di, fmaf(fs.y, sw, bv.y));
    reinterpret_cast<float2*>(out)[(size_t)gw * 32 + lane] = r;
}

// ---------------- launch ------------------------------------------------------
extern "C" void kernel_launch(void* const* d_in, const int* in_sizes, int n_in,
                              void* d_out, int out_size) {
    const float* x     = (const float*)d_in[0];
    const void*  edges = d_in[1];                 // edge_index [2, E], int32 or int64
    const float* W1    = (const float*)d_in[2];
    const float* b1    = (const float*)d_in[3];
    const float* W2    = (const float*)d_in[4];
    const float* b2    = (const float*)d_in[5];
    float*       out   = (float*)d_out;

    const int E = in_sizes[1] / 2;     // 800000
    const int N = in_sizes[0] / FIN;   // 50000

    const int nb256_E = (E + 255) / 256;
    const int nb_scan = (N + SCAN_TILE - 1) / SCAN_TILE;

    // CSR build: 4 spin-free kernels
    k_deg_count<<<nb256_E, 256>>>(edges, E, N);
    k_scan_a   <<<nb_scan, 256>>>(N);
    k_scan_b   <<<nb_scan, 256>>>(N, E);
    k_perm     <<<nb256_E, 256>>>(edges, E, N);

    // layer 1
    k_gemm1<<<(N + 127) / 128, 256>>>(x, W1, N);
    k_agg1 <<<(N * 32 + 255) / 256, 256>>>(b1, N);

    // layer 2
    k_gemm2<<<(N + 127) / 128, 128>>>(W2, N);
    k_agg2 <<<(N * 32 + 255) / 256, 256>>>(b2, out, N);
}

// round 9
// speedup vs baseline: 1.6609x; 1.2880x over previous
#include <cuda_runtime.h>
#include <cuda_fp16.h>
#include <cstdint>

// Problem-fixed sizes
#define MAX_N 50000
#define MAX_E 800000
#define FIN 128
#define HID 128
#define FOUT 64
#define SCAN_TILE 2048   // 256 threads * 8 elements

// R9 note: identical algorithm to R8 (audited: no spin loops, bounded indices,
// 40KB static smem < 48KB, regs OK). R8 bench died at container level twice;
// resubmitting to attribute infra vs kernel cleanly.

// ---------------- scratch (device globals; no allocation allowed) -----------
__device__ __align__(16) __half g_h1h[MAX_N * HID];   // x @ W1   (fp16 storage)
__device__ __align__(16) float  g_agg [MAX_N * HID];  // relu(agg(h1)) + b1 (fp32)
__device__ __align__(16) __half g_h2h[MAX_N * FOUT];  // agg @ W2 (fp16 storage)
__device__ float g_dinv[MAX_N];
__device__ __align__(16) int g_deg[MAX_N];            // zero-init; re-zeroed each pass
__device__ int   g_rowstart[MAX_N + 1];
__device__ int   g_cursor[MAX_N];
__device__ __align__(8) int2 g_epair[MAX_E];          // {src, dinv[src] bits}
__device__ int   g_tilesum[64];                       // per-tile degree sums
__device__ int   g_is64;                              // edge_index dtype flag

__device__ __forceinline__ int edge_at(const void* edges, int is64, long long idx) {
    if (is64) return (int)((const long long*)edges)[idx];
    return ((const int*)edges)[idx];
}

// ---------------- degree count (+ dtype probe) -------------------------------
__global__ void k_deg_count(const void* __restrict__ edges, int E, int N) {
    __shared__ int sh_is64;
    if (threadIdx.x < 32) {
        int n = (E < 32) ? E : 32;
        int ok = 1;
        if ((int)threadIdx.x < n) {
            long long v = ((const long long*)edges)[threadIdx.x];
            ok = (v >= 0 && v < N);
        }
        unsigned mask = __ballot_sync(0xffffffffu, ok);
        if (threadIdx.x == 0) {
            sh_is64 = (mask == 0xffffffffu);
            if (blockIdx.x == 0) g_is64 = sh_is64;
        }
    }
    __syncthreads();
    int is64 = sh_is64;

    int e = blockIdx.x * blockDim.x + threadIdx.x;
    if (e < E) {
        int d = edge_at(edges, is64, (long long)E + e);
        if ((unsigned)d < (unsigned)N) atomicAdd(&g_deg[d], 1);
    }
}

// ---------------- spin-free two-kernel scan ----------------------------------
__global__ void k_scan_a(int N) {
    __shared__ int s[256];
    const int t = threadIdx.x;
    const int b = blockIdx.x;
    const int base = b * SCAN_TILE + t * 8;

    int sum = 0;
    if (base + 7 < N) {
        int4 p0 = *reinterpret_cast<const int4*>(&g_deg[base]);
        int4 p1 = *reinterpret_cast<const int4*>(&g_deg[base + 4]);
        sum = p0.x + p0.y + p0.z + p0.w + p1.x + p1.y + p1.z + p1.w;
    } else {
        #pragma unroll
        for (int j = 0; j < 8; j++) {
            int i = base + j;
            if (i < N) sum += g_deg[i];
        }
    }
    s[t] = sum;
    __syncthreads();
    #pragma unroll
    for (int off = 128; off; off >>= 1) {
        if (t < off) s[t] += s[t + off];
        __syncthreads();
    }
    if (t == 0) g_tilesum[b] = s[0];
}

__global__ void k_scan_b(int N, int E) {
    __shared__ int s[256];
    __shared__ int s_prefix;
    const int t = threadIdx.x;
    const int b = blockIdx.x;
    const int base = b * SCAN_TILE + t * 8;

    int v[8];
    int sum = 0;
    if (base + 7 < N) {
        int4 p0 = *reinterpret_cast<const int4*>(&g_deg[base]);
        int4 p1 = *reinterpret_cast<const int4*>(&g_deg[base + 4]);
        v[0]=p0.x; v[1]=p0.y; v[2]=p0.z; v[3]=p0.w;
        v[4]=p1.x; v[5]=p1.y; v[6]=p1.z; v[7]=p1.w;
        *reinterpret_cast<int4*>(&g_deg[base])     = make_int4(0,0,0,0);
        *reinterpret_cast<int4*>(&g_deg[base + 4]) = make_int4(0,0,0,0);
        #pragma unroll
        for (int j = 0; j < 8; j++) {
            g_dinv[base + j] = rsqrtf((float)(v[j] + 1));  // +1 self loop
            sum += v[j];
        }
    } else {
        #pragma unroll
        for (int j = 0; j < 8; j++) {
            int i = base + j;
            int d = (i < N) ? g_deg[i] : 0;
            v[j] = d;
            if (i < N) { g_deg[i] = 0; g_dinv[i] = rsqrtf((float)(d + 1)); }
            sum += d;
        }
    }

    s[t] = sum;
    __syncthreads();
    #pragma unroll
    for (int off = 1; off < 256; off <<= 1) {
        int x = (t >= off) ? s[t - off] : 0;
        __syncthreads();
        s[t] += x;
        __syncthreads();
    }
    const int thr_excl = s[t] - sum;

    if (t < 32) {
        int prefix = 0;
        for (int p = t; p < b; p += 32) prefix += g_tilesum[p];
        #pragma unroll
        for (int off = 16; off; off >>= 1)
            prefix += __shfl_xor_sync(0xffffffffu, prefix, off);
        if (t == 0) s_prefix = prefix;
    }
    __syncthreads();

    int pos = s_prefix + thr_excl;
    #pragma unroll
    for (int j = 0; j < 8; j++) {
        int i = base + j;
        if (i < N) { g_rowstart[i] = pos; g_cursor[i] = pos; }
        pos += v[j];
    }
    if (b == 0 && t == 0) g_rowstart[N] = E;
}

__global__ void k_perm(const void* __restrict__ edges, int E, int N) {
    int e = blockIdx.x * blockDim.x + threadIdx.x;
    if (e < E) {
        int is64 = g_is64;
        int s = edge_at(edges, is64, e);
        int d = edge_at(edges, is64, (long long)E + e);
        if ((unsigned)d < (unsigned)N && (unsigned)s < (unsigned)N) {
            int pos = atomicAdd(&g_cursor[d], 1);
            g_epair[pos] = make_int2(s, __float_as_int(g_dinv[s]));
        }
    }
}

// ---------------- fp16 tensor-core GEMM (mma.sync m16n8k16) ------------------
// C_half[M,BN] = A_f32[M,Kd] @ W_f32[Kd,BN]; inputs converted fp32->fp16 during
// smem staging, fp32 accumulate, fp16 store. BN == full N (blocks tile M only).
__device__ __forceinline__ void mma16816(float* c, const unsigned* a, const unsigned* b) {
    asm volatile(
        "mma.sync.aligned.m16n8k16.row.col.f32.f16.f16.f32 "
        "{%0,%1,%2,%3}, {%4,%5,%6,%7}, {%8,%9}, {%0,%1,%2,%3};\n"
        : "+f"(c[0]), "+f"(c[1]), "+f"(c[2]), "+f"(c[3])
        : "r"(a[0]), "r"(a[1]), "r"(a[2]), "r"(a[3]), "r"(b[0]), "r"(b[1]));
}

template<int BM, int BN, int BK, int THREADS, int WARPS_M, int WARPS_N>
__device__ __forceinline__ void gemm_hmma(const float* __restrict__ A,
                                          const float* __restrict__ W,
                                          __half* __restrict__ C,
                                          int M, int Kd) {
    constexpr int WM = BM / WARPS_M;       // 32
    constexpr int WN = BN / WARPS_N;       // 64 or 32
    constexpr int MT = WM / 16;            // 2
    constexpr int NT = WN / 8;             // 8 or 4
    constexpr int LDA = BK + 8;            // 40 halves = 80B: 16B-mult, conflict-free
    constexpr int LDB = BK + 8;
    constexpr int A_IT = (BM * BK / 8) / THREADS;
    constexpr int B_IT = (BK * BN / 8) / THREADS;

    __shared__ __half As[2][BM][LDA];
    __shared__ __half Bs[2][BN][LDB];      // n-major (transposed): Bs[n][k]

    const int tid  = threadIdx.x;
    const int wid  = tid >> 5;
    const int lane = tid & 31;
    const int g    = lane >> 2;
    const int tg   = lane & 3;
    const int wm0  = (wid % WARPS_M) * WM;
    const int wn0  = (wid / WARPS_M) * WN;
    const int row0 = blockIdx.x * BM;

    float acc[MT][NT][4];
    #pragma unroll
    for (int i = 0; i < MT; i++)
        #pragma unroll
        for (int j = 0; j < NT; j++)
            #pragma unroll
            for (int q = 0; q < 4; q++) acc[i][j][q] = 0.f;

    float aStage[A_IT][8];
    float bStage[B_IT][8];

    auto ldg_tiles = [&](int kc) {
        #pragma unroll
        for (int t = 0; t < A_IT; t++) {
            int idx = tid + t * THREADS;
            int m   = idx / (BK / 8);
            int k8  = (idx % (BK / 8)) * 8;
            int gr  = row0 + m;
            if (gr < M) {
                float4 f0 = *reinterpret_cast<const float4*>(A + (size_t)gr * Kd + kc + k8);
                float4 f1 = *reinterpret_cast<const float4*>(A + (size_t)gr * Kd + kc + k8 + 4);
                aStage[t][0]=f0.x; aStage[t][1]=f0.y; aStage[t][2]=f0.z; aStage[t][3]=f0.w;
                aStage[t][4]=f1.x; aStage[t][5]=f1.y; aStage[t][6]=f1.z; aStage[t][7]=f1.w;
            } else {
                #pragma unroll
                for (int q = 0; q < 8; q++) aStage[t][q] = 0.f;
            }
        }
        #pragma unroll
        for (int t = 0; t < B_IT; t++) {
            int idx = tid + t * THREADS;
            int k   = idx / (BN / 8);
            int n8  = (idx % (BN / 8)) * 8;
            float4 f0 = *reinterpret_cast<const float4*>(W + (size_t)(kc + k) * BN + n8);
            float4 f1 = *reinterpret_cast<const float4*>(W + (size_t)(kc + k) * BN + n8 + 4);
            bStage[t][0]=f0.x; bStage[t][1]=f0.y; bStage[t][2]=f0.z; bStage[t][3]=f0.w;
            bStage[t][4]=f1.x; bStage[t][5]=f1.y; bStage[t][6]=f1.z; bStage[t][7]=f1.w;
        }
    };
    auto sts_tiles = [&](int buf) {
        #pragma unroll
        for (int t = 0; t < A_IT; t++) {
            int idx = tid + t * THREADS;
            int m   = idx / (BK / 8);
            int k8  = (idx % (BK / 8)) * 8;
            __half2 h0 = __floats2half2_rn(aStage[t][0], aStage[t][1]);
            __half2 h1 = __floats2half2_rn(aStage[t][2], aStage[t][3]);
            __half2 h2 = __floats2half2_rn(aStage[t][4], aStage[t][5]);
            __half2 h3 = __floats2half2_rn(aStage[t][6], aStage[t][7]);
            uint4 u = make_uint4(*reinterpret_cast<unsigned*>(&h0),
                                 *reinterpret_cast<unsigned*>(&h1),
                                 *reinterpret_cast<unsigned*>(&h2),
                                 *reinterpret_cast<unsigned*>(&h3));
            *reinterpret_cast<uint4*>(&As[buf][m][k8]) = u;   // 80B row stride: 16B-aligned
        }
        #pragma unroll
        for (int t = 0; t < B_IT; t++) {
            int idx = tid + t * THREADS;
            int k   = idx / (BN / 8);
            int n8  = (idx % (BN / 8)) * 8;
            #pragma unroll
            for (int q = 0; q < 8; q++)
                Bs[buf][n8 + q][k] = __float2half_rn(bStage[t][q]);
        }
    };

    ldg_tiles(0);
    sts_tiles(0);
    __syncthreads();

    const int T = Kd / BK;
    for (int t = 0; t < T; t++) {
        const int buf = t & 1;
        if (t + 1 < T) ldg_tiles((t + 1) * BK);

        #pragma unroll
        for (int kk = 0; kk < BK; kk += 16) {
            unsigned af[MT][4];
            unsigned bf[NT][2];
            #pragma unroll
            for (int mt = 0; mt < MT; mt++) {
                int r0 = wm0 + mt * 16;
                af[mt][0] = *reinterpret_cast<const unsigned*>(&As[buf][r0 + g    ][kk + 2*tg    ]);
                af[mt][1] = *reinterpret_cast<const unsigned*>(&As[buf][r0 + g + 8][kk + 2*tg    ]);
                af[mt][2] = *reinterpret_cast<const unsigned*>(&As[buf][r0 + g    ][kk + 2*tg + 8]);
                af[mt][3] = *reinterpret_cast<const unsigned*>(&As[buf][r0 + g + 8][kk + 2*tg + 8]);
            }
            #pragma unroll
            for (int nt = 0; nt < NT; nt++) {
                int n = wn0 + nt * 8 + g;
                bf[nt][0] = *reinterpret_cast<const unsigned*>(&Bs[buf][n][kk + 2*tg    ]);
                bf[nt][1] = *reinterpret_cast<const unsigned*>(&Bs[buf][n][kk + 2*tg + 8]);
            }
            #pragma unroll
            for (int mt = 0; mt < MT; mt++)
                #pragma unroll
                for (int nt = 0; nt < NT; nt++)
                    mma16816(acc[mt][nt], af[mt], bf[nt]);
        }

        if (t + 1 < T) {
            sts_tiles(buf ^ 1);
            __syncthreads();
        }
    }

    // epilogue: fp32 -> fp16 pairs, 4B stores
    #pragma unroll
    for (int mt = 0; mt < MT; mt++) {
        int ra = row0 + wm0 + mt * 16 + g;
        int rb = ra + 8;
        #pragma unroll
        for (int nt = 0; nt < NT; nt++) {
            int c = wn0 + nt * 8 + 2 * tg;
            if (ra < M) {
                __half2 h = __floats2half2_rn(acc[mt][nt][0], acc[mt][nt][1]);
                *reinterpret_cast<__half2*>(C + (size_t)ra * BN + c) = h;
            }
            if (rb < M) {
                __half2 h = __floats2half2_rn(acc[mt][nt][2], acc[mt][nt][3]);
                *reinterpret_cast<__half2*>(C + (size_t)rb * BN + c) = h;
            }
        }
    }
}

__global__ void __launch_bounds__(256)
k_gemm1(const float* __restrict__ x, const float* __restrict__ W1, int M) {
    gemm_hmma<128, 128, 32, 256, 4, 2>(x, W1, g_h1h, M, FIN);
}

__global__ void __launch_bounds__(256)
k_gemm2(const float* __restrict__ W2, int M) {
    gemm_hmma<128, 64, 32, 256, 4, 2>(g_agg, W2, g_h2h, M, HID);
}

// ---------------- gather aggregation (one warp per node, no atomics) --------
__global__ void k_agg1(const float* __restrict__ bias, int N) {
    int gw   = (blockIdx.x * blockDim.x + threadIdx.x) >> 5;
    int lane = threadIdx.x & 31;
    if (gw >= N) return;
    const int start = g_rowstart[gw];
    const int end   = g_rowstart[gw + 1];

    const uint2* __restrict__ hp = reinterpret_cast<const uint2*>(g_h1h);
    float4 acc = make_float4(0.f, 0.f, 0.f, 0.f);

    #pragma unroll 4
    for (int e = start; e < end; e++) {
        int2  pr = g_epair[e];                 // uniform across warp
        float w  = __int_as_float(pr.y);
        uint2 rv = hp[(size_t)pr.x * 32 + lane];
        float2 f0 = __half22float2(*reinterpret_cast<__half2*>(&rv.x));
        float2 f1 = __half22float2(*reinterpret_cast<__half2*>(&rv.y));
        acc.x = fmaf(f0.x, w, acc.x);
        acc.y = fmaf(f0.y, w, acc.y);
        acc.z = fmaf(f1.x, w, acc.z);
        acc.w = fmaf(f1.y, w, acc.w);
    }

    float di = g_dinv[gw];
    float sw = di * di;
    uint2 rs = hp[(size_t)gw * 32 + lane];
    float2 s0 = __half22float2(*reinterpret_cast<__half2*>(&rs.x));
    float2 s1 = __half22float2(*reinterpret_cast<__half2*>(&rs.y));
    float4 bv = reinterpret_cast<const float4*>(bias)[lane];
    float4 r;
    r.x = fmaxf(fmaf(acc.x, di, fmaf(s0.x, sw, bv.x)), 0.f);
    r.y = fmaxf(fmaf(acc.y, di, fmaf(s0.y, sw, bv.y)), 0.f);
    r.z = fmaxf(fmaf(acc.z, di, fmaf(s1.x, sw, bv.z)), 0.f);
    r.w = fmaxf(fmaf(acc.w, di, fmaf(s1.y, sw, bv.w)), 0.f);
    reinterpret_cast<float4*>(g_agg)[(size_t)gw * 32 + lane] = r;
}

__global__ void k_agg2(const float* __restrict__ bias, float* __restrict__ out, int N) {
    int gw   = (blockIdx.x * blockDim.x + threadIdx.x) >> 5;
    int lane = threadIdx.x & 31;
    if (gw >= N) return;
    const int start = g_rowstart[gw];
    const int end   = g_rowstart[gw + 1];

    const __half2* __restrict__ hp = reinterpret_cast<const __half2*>(g_h2h);
    float2 acc = make_float2(0.f, 0.f);

    #pragma unroll 4
    for (int e = start; e < end; e++) {
        int2  pr = g_epair[e];                 // uniform across warp
        float w  = __int_as_float(pr.y);
        float2 f = __half22float2(hp[(size_t)pr.x * 32 + lane]);
        acc.x = fmaf(f.x, w, acc.x);
        acc.y = fmaf(f.y, w, acc.y);
    }

    float di = g_dinv[gw];
    float sw = di * di;
    float2 fs = __half22float2(hp[(size_t)gw * 32 + lane]);
    float2 bv = reinterpret_cast<const float2*>(bias)[lane];
    float2 r;
    r.x = fmaf(acc.x, di, fmaf(fs.x, sw, bv.x));
    r.y = fmaf(acc.y, di, fmaf(fs.y, sw, bv.y));
    reinterpret_cast<float2*>(out)[(size_t)gw * 32 + lane] = r;
}

// ---------------- launch ------------------------------------------------------
extern "C" void kernel_launch(void* const* d_in, const int* in_sizes, int n_in,
                              void* d_out, int out_size) {
    const float* x     = (const float*)d_in[0];
    const void*  edges = d_in[1];                 // edge_index [2, E], int32 or int64
    const float* W1    = (const float*)d_in[2];
    const float* b1    = (const float*)d_in[3];
    const float* W2    = (const float*)d_in[4];
    const float* b2    = (const float*)d_in[5];
    float*       out   = (float*)d_out;

    const int E = in_sizes[1] / 2;     // 800000
    const int N = in_sizes[0] / FIN;   // 50000

    const int nb256_E = (E + 255) / 256;
    const int nb_scan = (N + SCAN_TILE - 1) / SCAN_TILE;

    // CSR build: 4 spin-free kernels
    k_deg_count<<<nb256_E, 256>>>(edges, E, N);
    k_scan_a   <<<nb_scan, 256>>>(N);
    k_scan_b   <<<nb_scan, 256>>>(N, E);
    k_perm     <<<nb256_E, 256>>>(edges, E, N);

    // layer 1
    k_gemm1<<<(N + 127) / 128, 256>>>(x, W1, N);
    k_agg1 <<<(N * 32 + 255) / 256, 256>>>(b1, N);

    // layer 2
    k_gemm2<<<(N + 127) / 128, 256>>>(W2, N);
    k_agg2 <<<(N * 32 + 255) / 256, 256>>>(b2, out, N);
}

// round 10
// speedup vs baseline: 1.7546x; 1.0564x over previous
#include <cuda_runtime.h>
#include <cuda_fp16.h>
#include <cstdint>

// Problem-fixed sizes
#define MAX_N 50000
#define MAX_E 800000
#define FIN 128
#define HID 128
#define FOUT 64
#define SCAN_TILE 2048   // 256 threads * 8 elements

// R10: compute kernels identical to R9 (122.9us). Change: graph-level
// parallelism — k_gemm1 (independent of edges) forks onto a side stream and
// joins before k_agg1, hiding it behind the CSR-build chain.

// ---------------- scratch (device globals; no allocation allowed) -----------
__device__ __align__(16) __half g_h1h[MAX_N * HID];   // x @ W1   (fp16 storage)
__device__ __align__(16) float  g_agg [MAX_N * HID];  // relu(agg(h1)) + b1 (fp32)
__device__ __align__(16) __half g_h2h[MAX_N * FOUT];  // agg @ W2 (fp16 storage)
__device__ float g_dinv[MAX_N];
__device__ __align__(16) int g_deg[MAX_N];            // zero-init; re-zeroed each pass
__device__ int   g_rowstart[MAX_N + 1];
__device__ int   g_cursor[MAX_N];
__device__ __align__(8) int2 g_epair[MAX_E];          // {src, dinv[src] bits}
__device__ int   g_tilesum[64];                       // per-tile degree sums
__device__ int   g_is64;                              // edge_index dtype flag

__device__ __forceinline__ int edge_at(const void* edges, int is64, long long idx) {
    if (is64) return (int)((const long long*)edges)[idx];
    return ((const int*)edges)[idx];
}

// ---------------- degree count (+ dtype probe) -------------------------------
__global__ void k_deg_count(const void* __restrict__ edges, int E, int N) {
    __shared__ int sh_is64;
    if (threadIdx.x < 32) {
        int n = (E < 32) ? E : 32;
        int ok = 1;
        if ((int)threadIdx.x < n) {
            long long v = ((const long long*)edges)[threadIdx.x];
            ok = (v >= 0 && v < N);
        }
        unsigned mask = __ballot_sync(0xffffffffu, ok);
        if (threadIdx.x == 0) {
            sh_is64 = (mask == 0xffffffffu);
            if (blockIdx.x == 0) g_is64 = sh_is64;
        }
    }
    __syncthreads();
    int is64 = sh_is64;

    int e = blockIdx.x * blockDim.x + threadIdx.x;
    if (e < E) {
        int d = edge_at(edges, is64, (long long)E + e);
        if ((unsigned)d < (unsigned)N) atomicAdd(&g_deg[d], 1);
    }
}

// ---------------- spin-free two-kernel scan ----------------------------------
__global__ void k_scan_a(int N) {
    __shared__ int s[256];
    const int t = threadIdx.x;
    const int b = blockIdx.x;
    const int base = b * SCAN_TILE + t * 8;

    int sum = 0;
    if (base + 7 < N) {
        int4 p0 = *reinterpret_cast<const int4*>(&g_deg[base]);
        int4 p1 = *reinterpret_cast<const int4*>(&g_deg[base + 4]);
        sum = p0.x + p0.y + p0.z + p0.w + p1.x + p1.y + p1.z + p1.w;
    } else {
        #pragma unroll
        for (int j = 0; j < 8; j++) {
            int i = base + j;
            if (i < N) sum += g_deg[i];
        }
    }
    s[t] = sum;
    __syncthreads();
    #pragma unroll
    for (int off = 128; off; off >>= 1) {
        if (t < off) s[t] += s[t + off];
        __syncthreads();
    }
    if (t == 0) g_tilesum[b] = s[0];
}

__global__ void k_scan_b(int N, int E) {
    __shared__ int s[256];
    __shared__ int s_prefix;
    const int t = threadIdx.x;
    const int b = blockIdx.x;
    const int base = b * SCAN_TILE + t * 8;

    int v[8];
    int sum = 0;
    if (base + 7 < N) {
        int4 p0 = *reinterpret_cast<const int4*>(&g_deg[base]);
        int4 p1 = *reinterpret_cast<const int4*>(&g_deg[base + 4]);
        v[0]=p0.x; v[1]=p0.y; v[2]=p0.z; v[3]=p0.w;
        v[4]=p1.x; v[5]=p1.y; v[6]=p1.z; v[7]=p1.w;
        *reinterpret_cast<int4*>(&g_deg[base])     = make_int4(0,0,0,0);
        *reinterpret_cast<int4*>(&g_deg[base + 4]) = make_int4(0,0,0,0);
        #pragma unroll
        for (int j = 0; j < 8; j++) {
            g_dinv[base + j] = rsqrtf((float)(v[j] + 1));  // +1 self loop
            sum += v[j];
        }
    } else {
        #pragma unroll
        for (int j = 0; j < 8; j++) {
            int i = base + j;
            int d = (i < N) ? g_deg[i] : 0;
            v[j] = d;
            if (i < N) { g_deg[i] = 0; g_dinv[i] = rsqrtf((float)(d + 1)); }
            sum += d;
        }
    }

    s[t] = sum;
    __syncthreads();
    #pragma unroll
    for (int off = 1; off < 256; off <<= 1) {
        int x = (t >= off) ? s[t - off] : 0;
        __syncthreads();
        s[t] += x;
        __syncthreads();
    }
    const int thr_excl = s[t] - sum;

    if (t < 32) {
        int prefix = 0;
        for (int p = t; p < b; p += 32) prefix += g_tilesum[p];
        #pragma unroll
        for (int off = 16; off; off >>= 1)
            prefix += __shfl_xor_sync(0xffffffffu, prefix, off);
        if (t == 0) s_prefix = prefix;
    }
    __syncthreads();

    int pos = s_prefix + thr_excl;
    #pragma unroll
    for (int j = 0; j < 8; j++) {
        int i = base + j;
        if (i < N) { g_rowstart[i] = pos; g_cursor[i] = pos; }
        pos += v[j];
    }
    if (b == 0 && t == 0) g_rowstart[N] = E;
}

__global__ void k_perm(const void* __restrict__ edges, int E, int N) {
    int e = blockIdx.x * blockDim.x + threadIdx.x;
    if (e < E) {
        int is64 = g_is64;
        int s = edge_at(edges, is64, e);
        int d = edge_at(edges, is64, (long long)E + e);
        if ((unsigned)d < (unsigned)N && (unsigned)s < (unsigned)N) {
            int pos = atomicAdd(&g_cursor[d], 1);
            g_epair[pos] = make_int2(s, __float_as_int(g_dinv[s]));
        }
    }
}

// ---------------- fp16 tensor-core GEMM (mma.sync m16n8k16) ------------------
__device__ __forceinline__ void mma16816(float* c, const unsigned* a, const unsigned* b) {
    asm volatile(
        "mma.sync.aligned.m16n8k16.row.col.f32.f16.f16.f32 "
        "{%0,%1,%2,%3}, {%4,%5,%6,%7}, {%8,%9}, {%0,%1,%2,%3};\n"
        : "+f"(c[0]), "+f"(c[1]), "+f"(c[2]), "+f"(c[3])
        : "r"(a[0]), "r"(a[1]), "r"(a[2]), "r"(a[3]), "r"(b[0]), "r"(b[1]));
}

template<int BM, int BN, int BK, int THREADS, int WARPS_M, int WARPS_N>
__device__ __forceinline__ void gemm_hmma(const float* __restrict__ A,
                                          const float* __restrict__ W,
                                          __half* __restrict__ C,
                                          int M, int Kd) {
    constexpr int WM = BM / WARPS_M;       // 32
    constexpr int WN = BN / WARPS_N;       // 64 or 32
    constexpr int MT = WM / 16;            // 2
    constexpr int NT = WN / 8;             // 8 or 4
    constexpr int LDA = BK + 8;            // 40 halves = 80B: 16B-mult, conflict-free
    constexpr int LDB = BK + 8;
    constexpr int A_IT = (BM * BK / 8) / THREADS;
    constexpr int B_IT = (BK * BN / 8) / THREADS;

    __shared__ __half As[2][BM][LDA];
    __shared__ __half Bs[2][BN][LDB];      // n-major (transposed): Bs[n][k]

    const int tid  = threadIdx.x;
    const int wid  = tid >> 5;
    const int lane = tid & 31;
    const int g    = lane >> 2;
    const int tg   = lane & 3;
    const int wm0  = (wid % WARPS_M) * WM;
    const int wn0  = (wid / WARPS_M) * WN;
    const int row0 = blockIdx.x * BM;

    float acc[MT][NT][4];
    #pragma unroll
    for (int i = 0; i < MT; i++)
        #pragma unroll
        for (int j = 0; j < NT; j++)
            #pragma unroll
            for (int q = 0; q < 4; q++) acc[i][j][q] = 0.f;

    float aStage[A_IT][8];
    float bStage[B_IT][8];

    auto ldg_tiles = [&](int kc) {
        #pragma unroll
        for (int t = 0; t < A_IT; t++) {
            int idx = tid + t * THREADS;
            int m   = idx / (BK / 8);
            int k8  = (idx % (BK / 8)) * 8;
            int gr  = row0 + m;
            if (gr < M) {
                float4 f0 = *reinterpret_cast<const float4*>(A + (size_t)gr * Kd + kc + k8);
                float4 f1 = *reinterpret_cast<const float4*>(A + (size_t)gr * Kd + kc + k8 + 4);
                aStage[t][0]=f0.x; aStage[t][1]=f0.y; aStage[t][2]=f0.z; aStage[t][3]=f0.w;
                aStage[t][4]=f1.x; aStage[t][5]=f1.y; aStage[t][6]=f1.z; aStage[t][7]=f1.w;
            } else {
                #pragma unroll
                for (int q = 0; q < 8; q++) aStage[t][q] = 0.f;
            }
        }
        #pragma unroll
        for (int t = 0; t < B_IT; t++) {
            int idx = tid + t * THREADS;
            int k   = idx / (BN / 8);
            int n8  = (idx % (BN / 8)) * 8;
            float4 f0 = *reinterpret_cast<const float4*>(W + (size_t)(kc + k) * BN + n8);
            float4 f1 = *reinterpret_cast<const float4*>(W + (size_t)(kc + k) * BN + n8 + 4);
            bStage[t][0]=f0.x; bStage[t][1]=f0.y; bStage[t][2]=f0.z; bStage[t][3]=f0.w;
            bStage[t][4]=f1.x; bStage[t][5]=f1.y; bStage[t][6]=f1.z; bStage[t][7]=f1.w;
        }
    };
    auto sts_tiles = [&](int buf) {
        #pragma unroll
        for (int t = 0; t < A_IT; t++) {
            int idx = tid + t * THREADS;
            int m   = idx / (BK / 8);
            int k8  = (idx % (BK / 8)) * 8;
            __half2 h0 = __floats2half2_rn(aStage[t][0], aStage[t][1]);
            __half2 h1 = __floats2half2_rn(aStage[t][2], aStage[t][3]);
            __half2 h2 = __floats2half2_rn(aStage[t][4], aStage[t][5]);
            __half2 h3 = __floats2half2_rn(aStage[t][6], aStage[t][7]);
            uint4 u = make_uint4(*reinterpret_cast<unsigned*>(&h0),
                                 *reinterpret_cast<unsigned*>(&h1),
                                 *reinterpret_cast<unsigned*>(&h2),
                                 *reinterpret_cast<unsigned*>(&h3));
            *reinterpret_cast<uint4*>(&As[buf][m][k8]) = u;   // 80B row stride: 16B-aligned
        }
        #pragma unroll
        for (int t = 0; t < B_IT; t++) {
            int idx = tid + t * THREADS;
            int k   = idx / (BN / 8);
            int n8  = (idx % (BN / 8)) * 8;
            #pragma unroll
            for (int q = 0; q < 8; q++)
                Bs[buf][n8 + q][k] = __float2half_rn(bStage[t][q]);
        }
    };

    ldg_tiles(0);
    sts_tiles(0);
    __syncthreads();

    const int T = Kd / BK;
    for (int t = 0; t < T; t++) {
        const int buf = t & 1;
        if (t + 1 < T) ldg_tiles((t + 1) * BK);

        #pragma unroll
        for (int kk = 0; kk < BK; kk += 16) {
            unsigned af[MT][4];
            unsigned bf[NT][2];
            #pragma unroll
            for (int mt = 0; mt < MT; mt++) {
                int r0 = wm0 + mt * 16;
                af[mt][0] = *reinterpret_cast<const unsigned*>(&As[buf][r0 + g    ][kk + 2*tg    ]);
                af[mt][1] = *reinterpret_cast<const unsigned*>(&As[buf][r0 + g + 8][kk + 2*tg    ]);
                af[mt][2] = *reinterpret_cast<const unsigned*>(&As[buf][r0 + g    ][kk + 2*tg + 8]);
                af[mt][3] = *reinterpret_cast<const unsigned*>(&As[buf][r0 + g + 8][kk + 2*tg + 8]);
            }
            #pragma unroll
            for (int nt = 0; nt < NT; nt++) {
                int n = wn0 + nt * 8 + g;
                bf[nt][0] = *reinterpret_cast<const unsigned*>(&Bs[buf][n][kk + 2*tg    ]);
                bf[nt][1] = *reinterpret_cast<const unsigned*>(&Bs[buf][n][kk + 2*tg + 8]);
            }
            #pragma unroll
            for (int mt = 0; mt < MT; mt++)
                #pragma unroll
                for (int nt = 0; nt < NT; nt++)
                    mma16816(acc[mt][nt], af[mt], bf[nt]);
        }

        if (t + 1 < T) {
            sts_tiles(buf ^ 1);
            __syncthreads();
        }
    }

    // epilogue: fp32 -> fp16 pairs, 4B stores
    #pragma unroll
    for (int mt = 0; mt < MT; mt++) {
        int ra = row0 + wm0 + mt * 16 + g;
        int rb = ra + 8;
        #pragma unroll
        for (int nt = 0; nt < NT; nt++) {
            int c = wn0 + nt * 8 + 2 * tg;
            if (ra < M) {
                __half2 h = __floats2half2_rn(acc[mt][nt][0], acc[mt][nt][1]);
                *reinterpret_cast<__half2*>(C + (size_t)ra * BN + c) = h;
            }
            if (rb < M) {
                __half2 h = __floats2half2_rn(acc[mt][nt][2], acc[mt][nt][3]);
                *reinterpret_cast<__half2*>(C + (size_t)rb * BN + c) = h;
            }
        }
    }
}

__global__ void __launch_bounds__(256)
k_gemm1(const float* __restrict__ x, const float* __restrict__ W1, int M) {
    gemm_hmma<128, 128, 32, 256, 4, 2>(x, W1, g_h1h, M, FIN);
}

__global__ void __launch_bounds__(256)
k_gemm2(const float* __restrict__ W2, int M) {
    gemm_hmma<128, 64, 32, 256, 4, 2>(g_agg, W2, g_h2h, M, HID);
}

// ---------------- gather aggregation (one warp per node, no atomics) --------
__global__ void k_agg1(const float* __restrict__ bias, int N) {
    int gw   = (blockIdx.x * blockDim.x + threadIdx.x) >> 5;
    int lane = threadIdx.x & 31;
    if (gw >= N) return;
    const int start = g_rowstart[gw];
    const int end   = g_rowstart[gw + 1];

    const uint2* __restrict__ hp = reinterpret_cast<const uint2*>(g_h1h);
    float4 acc = make_float4(0.f, 0.f, 0.f, 0.f);

    #pragma unroll 4
    for (int e = start; e < end; e++) {
        int2  pr = g_epair[e];                 // uniform across warp
        float w  = __int_as_float(pr.y);
        uint2 rv = hp[(size_t)pr.x * 32 + lane];
        float2 f0 = __half22float2(*reinterpret_cast<__half2*>(&rv.x));
        float2 f1 = __half22float2(*reinterpret_cast<__half2*>(&rv.y));
        acc.x = fmaf(f0.x, w, acc.x);
        acc.y = fmaf(f0.y, w, acc.y);
        acc.z = fmaf(f1.x, w, acc.z);
        acc.w = fmaf(f1.y, w, acc.w);
    }

    float di = g_dinv[gw];
    float sw = di * di;
    uint2 rs = hp[(size_t)gw * 32 + lane];
    float2 s0 = __half22float2(*reinterpret_cast<__half2*>(&rs.x));
    float2 s1 = __half22float2(*reinterpret_cast<__half2*>(&rs.y));
    float4 bv = reinterpret_cast<const float4*>(bias)[lane];
    float4 r;
    r.x = fmaxf(fmaf(acc.x, di, fmaf(s0.x, sw, bv.x)), 0.f);
    r.y = fmaxf(fmaf(acc.y, di, fmaf(s0.y, sw, bv.y)), 0.f);
    r.z = fmaxf(fmaf(acc.z, di, fmaf(s1.x, sw, bv.z)), 0.f);
    r.w = fmaxf(fmaf(acc.w, di, fmaf(s1.y, sw, bv.w)), 0.f);
    reinterpret_cast<float4*>(g_agg)[(size_t)gw * 32 + lane] = r;
}

__global__ void k_agg2(const float* __restrict__ bias, float* __restrict__ out, int N) {
    int gw   = (blockIdx.x * blockDim.x + threadIdx.x) >> 5;
    int lane = threadIdx.x & 31;
    if (gw >= N) return;
    const int start = g_rowstart[gw];
    const int end   = g_rowstart[gw + 1];

    const __half2* __restrict__ hp = reinterpret_cast<const __half2*>(g_h2h);
    float2 acc = make_float2(0.f, 0.f);

    #pragma unroll 4
    for (int e = start; e < end; e++) {
        int2  pr = g_epair[e];                 // uniform across warp
        float w  = __int_as_float(pr.y);
        float2 f = __half22float2(hp[(size_t)pr.x * 32 + lane]);
        acc.x = fmaf(f.x, w, acc.x);
        acc.y = fmaf(f.y, w, acc.y);
    }

    float di = g_dinv[gw];
    float sw = di * di;
    float2 fs = __half22float2(hp[(size_t)gw * 32 + lane]);
    float2 bv = reinterpret_cast<const float2*>(bias)[lane];
    float2 r;
    r.x = fmaf(acc.x, di, fmaf(fs.x, sw, bv.x));
    r.y = fmaf(acc.y, di, fmaf(fs.y, sw, bv.y));
    reinterpret_cast<float2*>(out)[(size_t)gw * 32 + lane] = r;
}

// ---------------- launch ------------------------------------------------------
extern "C" void kernel_launch(void* const* d_in, const int* in_sizes, int n_in,
                              void* d_out, int out_size) {
    const float* x     = (const float*)d_in[0];
    const void*  edges = d_in[1];                 // edge_index [2, E], int32 or int64
    const float* W1    = (const float*)d_in[2];
    const float* b1    = (const float*)d_in[3];
    const float* W2    = (const float*)d_in[4];
    const float* b2    = (const float*)d_in[5];
    float*       out   = (float*)d_out;

    const int E = in_sizes[1] / 2;     // 800000
    const int N = in_sizes[0] / FIN;   // 50000

    const int nb256_E = (E + 255) / 256;
    const int nb_scan = (N + SCAN_TILE - 1) / SCAN_TILE;

    // Fork-join: gemm1 (independent of edges) runs on a side stream in
    // parallel with the CSR build. Streams/events are host objects (no device
    // allocation); they intentionally outlive this call — capture-participating
    // streams must not be destroyed before the harness ends capture, and
    // kernel_launch is invoked only a handful of times.
    cudaStream_t s2;
    cudaEvent_t evFork, evJoin;
    cudaStreamCreateWithFlags(&s2, cudaStreamNonBlocking);
    cudaEventCreateWithFlags(&evFork, cudaEventDisableTiming);
    cudaEventCreateWithFlags(&evJoin, cudaEventDisableTiming);

    cudaEventRecord(evFork, 0);
    cudaStreamWaitEvent(s2, evFork, 0);
    k_gemm1<<<(N + 127) / 128, 256, 0, s2>>>(x, W1, N);    // side branch
    cudaEventRecord(evJoin, s2);

    // CSR build on the main (captured) stream
    k_deg_count<<<nb256_E, 256>>>(edges, E, N);
    k_scan_a   <<<nb_scan, 256>>>(N);
    k_scan_b   <<<nb_scan, 256>>>(N, E);
    k_perm     <<<nb256_E, 256>>>(edges, E, N);

    // join: agg1 needs both h1 (gemm1) and the CSR
    cudaStreamWaitEvent(0, evJoin, 0);
    k_agg1 <<<(N * 32 + 255) / 256, 256>>>(b1, N);

    // layer 2 (serial dependencies)
    k_gemm2<<<(N + 127) / 128, 256>>>(W2, N);
    k_agg2 <<<(N * 32 + 255) / 256, 256>>>(b2, out, N);
}

// round 11
// speedup vs baseline: 1.8042x; 1.0283x over previous
#include <cuda_runtime.h>
#include <cuda_fp16.h>
#include <cstdint>

// Problem-fixed sizes
#define MAX_N 50000
#define MAX_E 800000
#define FIN 128
#define HID 128
#define FOUT 64
#define SCAN_TILE 512    // 256 threads * 2 elements (98 blocks for N=50k)

// R11: R10 (116.3us) + (a) scan right-sized to 98 blocks, (b) g_agg stored
// fp16 (halves agg1 stores + gemm2 A-reads; gemm converts to half anyway).

// ---------------- scratch (device globals; no allocation allowed) -----------
__device__ __align__(16) __half g_h1h[MAX_N * HID];   // x @ W1   (fp16 storage)
__device__ __align__(16) __half g_aggh[MAX_N * HID];  // relu(agg(h1)) + b1 (fp16)
__device__ __align__(16) __half g_h2h[MAX_N * FOUT];  // agg @ W2 (fp16 storage)
__device__ float g_dinv[MAX_N];
__device__ __align__(16) int g_deg[MAX_N];            // zero-init; re-zeroed each pass
__device__ int   g_rowstart[MAX_N + 1];
__device__ int   g_cursor[MAX_N];
__device__ __align__(8) int2 g_epair[MAX_E];          // {src, dinv[src] bits}
__device__ int   g_tilesum[128];                      // per-tile degree sums
__device__ int   g_is64;                              // edge_index dtype flag

__device__ __forceinline__ int edge_at(const void* edges, int is64, long long idx) {
    if (is64) return (int)((const long long*)edges)[idx];
    return ((const int*)edges)[idx];
}

// ---------------- degree count (+ dtype probe) -------------------------------
__global__ void k_deg_count(const void* __restrict__ edges, int E, int N) {
    __shared__ int sh_is64;
    if (threadIdx.x < 32) {
        int n = (E < 32) ? E : 32;
        int ok = 1;
        if ((int)threadIdx.x < n) {
            long long v = ((const long long*)edges)[threadIdx.x];
            ok = (v >= 0 && v < N);
        }
        unsigned mask = __ballot_sync(0xffffffffu, ok);
        if (threadIdx.x == 0) {
            sh_is64 = (mask == 0xffffffffu);
            if (blockIdx.x == 0) g_is64 = sh_is64;
        }
    }
    __syncthreads();
    int is64 = sh_is64;

    int e = blockIdx.x * blockDim.x + threadIdx.x;
    if (e < E) {
        int d = edge_at(edges, is64, (long long)E + e);
        if ((unsigned)d < (unsigned)N) atomicAdd(&g_deg[d], 1);
    }
}

// ---------------- spin-free two-kernel scan (2 elems/thread) -----------------
__global__ void k_scan_a(int N) {
    __shared__ int s[256];
    const int t = threadIdx.x;
    const int b = blockIdx.x;
    const int base = b * SCAN_TILE + t * 2;

    int sum = 0;
    if (base + 1 < N) {
        int2 p = *reinterpret_cast<const int2*>(&g_deg[base]);
        sum = p.x + p.y;
    } else if (base < N) {
        sum = g_deg[base];
    }
    s[t] = sum;
    __syncthreads();
    #pragma unroll
    for (int off = 128; off; off >>= 1) {
        if (t < off) s[t] += s[t + off];
        __syncthreads();
    }
    if (t == 0) g_tilesum[b] = s[0];
}

__global__ void k_scan_b(int N, int E) {
    __shared__ int s[256];
    __shared__ int s_prefix;
    const int t = threadIdx.x;
    const int b = blockIdx.x;
    const int base = b * SCAN_TILE + t * 2;

    int v0 = 0, v1 = 0;
    if (base + 1 < N) {
        int2 p = *reinterpret_cast<const int2*>(&g_deg[base]);
        v0 = p.x; v1 = p.y;
        *reinterpret_cast<int2*>(&g_deg[base]) = make_int2(0, 0);
        g_dinv[base]     = rsqrtf((float)(v0 + 1));   // +1 self loop
        g_dinv[base + 1] = rsqrtf((float)(v1 + 1));
    } else if (base < N) {
        v0 = g_deg[base];
        g_deg[base] = 0;
        g_dinv[base] = rsqrtf((float)(v0 + 1));
    }
    int sum = v0 + v1;

    s[t] = sum;
    __syncthreads();
    #pragma unroll
    for (int off = 1; off < 256; off <<= 1) {
        int x = (t >= off) ? s[t - off] : 0;
        __syncthreads();
        s[t] += x;
        __syncthreads();
    }
    const int thr_excl = s[t] - sum;

    if (t < 32) {
        int prefix = 0;
        for (int p = t; p < b; p += 32) prefix += g_tilesum[p];
        #pragma unroll
        for (int off = 16; off; off >>= 1)
            prefix += __shfl_xor_sync(0xffffffffu, prefix, off);
        if (t == 0) s_prefix = prefix;
    }
    __syncthreads();

    int pos = s_prefix + thr_excl;
    if (base < N)     { g_rowstart[base]     = pos; g_cursor[base]     = pos; }
    if (base + 1 < N) { g_rowstart[base + 1] = pos + v0; g_cursor[base + 1] = pos + v0; }
    if (b == 0 && t == 0) g_rowstart[N] = E;
}

__global__ void k_perm(const void* __restrict__ edges, int E, int N) {
    int e = blockIdx.x * blockDim.x + threadIdx.x;
    if (e < E) {
        int is64 = g_is64;
        int s = edge_at(edges, is64, e);
        int d = edge_at(edges, is64, (long long)E + e);
        if ((unsigned)d < (unsigned)N && (unsigned)s < (unsigned)N) {
            int pos = atomicAdd(&g_cursor[d], 1);
            g_epair[pos] = make_int2(s, __float_as_int(g_dinv[s]));
        }
    }
}

// ---------------- fp16 tensor-core GEMM (mma.sync m16n8k16) ------------------
// C_half[M,BN] = A[M,Kd] @ W_f32[Kd,BN]; A is float (converted in staging) or
// __half (copied through). fp32 accumulate, fp16 store.
__device__ __forceinline__ void mma16816(float* c, const unsigned* a, const unsigned* b) {
    asm volatile(
        "mma.sync.aligned.m16n8k16.row.col.f32.f16.f16.f32 "
        "{%0,%1,%2,%3}, {%4,%5,%6,%7}, {%8,%9}, {%0,%1,%2,%3};\n"
        : "+f"(c[0]), "+f"(c[1]), "+f"(c[2]), "+f"(c[3])
        : "r"(a[0]), "r"(a[1]), "r"(a[2]), "r"(a[3]), "r"(b[0]), "r"(b[1]));
}

template<typename AT, int BM, int BN, int BK, int THREADS, int WARPS_M, int WARPS_N>
__device__ __forceinline__ void gemm_hmma(const AT* __restrict__ A,
                                          const float* __restrict__ W,
                                          __half* __restrict__ C,
                                          int M, int Kd) {
    constexpr int WM = BM / WARPS_M;       // 32
    constexpr int WN = BN / WARPS_N;       // 64 or 32
    constexpr int MT = WM / 16;            // 2
    constexpr int NT = WN / 8;             // 8 or 4
    constexpr int LDA = BK + 8;            // 40 halves = 80B: 16B-mult, conflict-free
    constexpr int LDB = BK + 8;
    constexpr int A_IT = (BM * BK / 8) / THREADS;
    constexpr int B_IT = (BK * BN / 8) / THREADS;
    constexpr bool A_HALF = sizeof(AT) == 2;

    __shared__ __half As[2][BM][LDA];
    __shared__ __half Bs[2][BN][LDB];      // n-major (transposed): Bs[n][k]

    const int tid  = threadIdx.x;
    const int wid  = tid >> 5;
    const int lane = tid & 31;
    const int g    = lane >> 2;
    const int tg   = lane & 3;
    const int wm0  = (wid % WARPS_M) * WM;
    const int wn0  = (wid / WARPS_M) * WN;
    const int row0 = blockIdx.x * BM;

    float acc[MT][NT][4];
    #pragma unroll
    for (int i = 0; i < MT; i++)
        #pragma unroll
        for (int j = 0; j < NT; j++)
            #pragma unroll
            for (int q = 0; q < 4; q++) acc[i][j][q] = 0.f;

    float aStageF[A_HALF ? 1 : A_IT][8];
    uint4 aStageH[A_HALF ? A_IT : 1];
    float bStage[B_IT][8];

    auto ldg_tiles = [&](int kc) {
        #pragma unroll
        for (int t = 0; t < A_IT; t++) {
            int idx = tid + t * THREADS;
            int m   = idx / (BK / 8);
            int k8  = (idx % (BK / 8)) * 8;
            int gr  = row0 + m;
            if constexpr (A_HALF) {
                aStageH[t] = (gr < M)
                    ? *reinterpret_cast<const uint4*>(A + (size_t)gr * Kd + kc + k8)
                    : make_uint4(0u, 0u, 0u, 0u);
            } else {
                if (gr < M) {
                    float4 f0 = *reinterpret_cast<const float4*>(A + (size_t)gr * Kd + kc + k8);
                    float4 f1 = *reinterpret_cast<const float4*>(A + (size_t)gr * Kd + kc + k8 + 4);
                    aStageF[t][0]=f0.x; aStageF[t][1]=f0.y; aStageF[t][2]=f0.z; aStageF[t][3]=f0.w;
                    aStageF[t][4]=f1.x; aStageF[t][5]=f1.y; aStageF[t][6]=f1.z; aStageF[t][7]=f1.w;
                } else {
                    #pragma unroll
                    for (int q = 0; q < 8; q++) aStageF[t][q] = 0.f;
                }
            }
        }
        #pragma unroll
        for (int t = 0; t < B_IT; t++) {
            int idx = tid + t * THREADS;
            int k   = idx / (BN / 8);
            int n8  = (idx % (BN / 8)) * 8;
            float4 f0 = *reinterpret_cast<const float4*>(W + (size_t)(kc + k) * BN + n8);
            float4 f1 = *reinterpret_cast<const float4*>(W + (size_t)(kc + k) * BN + n8 + 4);
            bStage[t][0]=f0.x; bStage[t][1]=f0.y; bStage[t][2]=f0.z; bStage[t][3]=f0.w;
            bStage[t][4]=f1.x; bStage[t][5]=f1.y; bStage[t][6]=f1.z; bStage[t][7]=f1.w;
        }
    };
    auto sts_tiles = [&](int buf) {
        #pragma unroll
        for (int t = 0; t < A_IT; t++) {
            int idx = tid + t * THREADS;
            int m   = idx / (BK / 8);
            int k8  = (idx % (BK / 8)) * 8;
            uint4 u;
            if constexpr (A_HALF) {
                u = aStageH[t];
            } else {
                __half2 h0 = __floats2half2_rn(aStageF[t][0], aStageF[t][1]);
                __half2 h1 = __floats2half2_rn(aStageF[t][2], aStageF[t][3]);
                __half2 h2 = __floats2half2_rn(aStageF[t][4], aStageF[t][5]);
                __half2 h3 = __floats2half2_rn(aStageF[t][6], aStageF[t][7]);
                u = make_uint4(*reinterpret_cast<unsigned*>(&h0),
                               *reinterpret_cast<unsigned*>(&h1),
                               *reinterpret_cast<unsigned*>(&h2),
                               *reinterpret_cast<unsigned*>(&h3));
            }
            *reinterpret_cast<uint4*>(&As[buf][m][k8]) = u;   // 80B row stride: 16B-aligned
        }
        #pragma unroll
        for (int t = 0; t < B_IT; t++) {
            int idx = tid + t * THREADS;
            int k   = idx / (BN / 8);
            int n8  = (idx % (BN / 8)) * 8;
            #pragma unroll
            for (int q = 0; q < 8; q++)
                Bs[buf][n8 + q][k] = __float2half_rn(bStage[t][q]);
        }
    };

    ldg_tiles(0);
    sts_tiles(0);
    __syncthreads();

    const int T = Kd / BK;
    for (int t = 0; t < T; t++) {
        const int buf = t & 1;
        if (t + 1 < T) ldg_tiles((t + 1) * BK);

        #pragma unroll
        for (int kk = 0; kk < BK; kk += 16) {
            unsigned af[MT][4];
            unsigned bf[NT][2];
            #pragma unroll
            for (int mt = 0; mt < MT; mt++) {
                int r0 = wm0 + mt * 16;
                af[mt][0] = *reinterpret_cast<const unsigned*>(&As[buf][r0 + g    ][kk + 2*tg    ]);
                af[mt][1] = *reinterpret_cast<const unsigned*>(&As[buf][r0 + g + 8][kk + 2*tg    ]);
                af[mt][2] = *reinterpret_cast<const unsigned*>(&As[buf][r0 + g    ][kk + 2*tg + 8]);
                af[mt][3] = *reinterpret_cast<const unsigned*>(&As[buf][r0 + g + 8][kk + 2*tg + 8]);
            }
            #pragma unroll
            for (int nt = 0; nt < NT; nt++) {
                int n = wn0 + nt * 8 + g;
                bf[nt][0] = *reinterpret_cast<const unsigned*>(&Bs[buf][n][kk + 2*tg    ]);
                bf[nt][1] = *reinterpret_cast<const unsigned*>(&Bs[buf][n][kk + 2*tg + 8]);
            }
            #pragma unroll
            for (int mt = 0; mt < MT; mt++)
                #pragma unroll
                for (int nt = 0; nt < NT; nt++)
                    mma16816(acc[mt][nt], af[mt], bf[nt]);
        }

        if (t + 1 < T) {
            sts_tiles(buf ^ 1);
            __syncthreads();
        }
    }

    // epilogue: fp32 -> fp16 pairs, 4B stores
    #pragma unroll
    for (int mt = 0; mt < MT; mt++) {
        int ra = row0 + wm0 + mt * 16 + g;
        int rb = ra + 8;
        #pragma unroll
        for (int nt = 0; nt < NT; nt++) {
            int c = wn0 + nt * 8 + 2 * tg;
            if (ra < M) {
                __half2 h = __floats2half2_rn(acc[mt][nt][0], acc[mt][nt][1]);
                *reinterpret_cast<__half2*>(C + (size_t)ra * BN + c) = h;
            }
            if (rb < M) {
                __half2 h = __floats2half2_rn(acc[mt][nt][2], acc[mt][nt][3]);
                *reinterpret_cast<__half2*>(C + (size_t)rb * BN + c) = h;
            }
        }
    }
}

__global__ void __launch_bounds__(256)
k_gemm1(const float* __restrict__ x, const float* __restrict__ W1, int M) {
    gemm_hmma<float, 128, 128, 32, 256, 4, 2>(x, W1, g_h1h, M, FIN);
}

__global__ void __launch_bounds__(256)
k_gemm2(const float* __restrict__ W2, int M) {
    gemm_hmma<__half, 128, 64, 32, 256, 4, 2>(g_aggh, W2, g_h2h, M, HID);
}

// ---------------- gather aggregation (one warp per node, no atomics) --------
__global__ void k_agg1(const float* __restrict__ bias, int N) {
    int gw   = (blockIdx.x * blockDim.x + threadIdx.x) >> 5;
    int lane = threadIdx.x & 31;
    if (gw >= N) return;
    const int start = g_rowstart[gw];
    const int end   = g_rowstart[gw + 1];

    const uint2* __restrict__ hp = reinterpret_cast<const uint2*>(g_h1h);
    float4 acc = make_float4(0.f, 0.f, 0.f, 0.f);

    #pragma unroll 4
    for (int e = start; e < end; e++) {
        int2  pr = g_epair[e];                 // uniform across warp
        float w  = __int_as_float(pr.y);
        uint2 rv = hp[(size_t)pr.x * 32 + lane];
        float2 f0 = __half22float2(*reinterpret_cast<__half2*>(&rv.x));
        float2 f1 = __half22float2(*reinterpret_cast<__half2*>(&rv.y));
        acc.x = fmaf(f0.x, w, acc.x);
        acc.y = fmaf(f0.y, w, acc.y);
        acc.z = fmaf(f1.x, w, acc.z);
        acc.w = fmaf(f1.y, w, acc.w);
    }

    float di = g_dinv[gw];
    float sw = di * di;
    uint2 rs = hp[(size_t)gw * 32 + lane];
    float2 s0 = __half22float2(*reinterpret_cast<__half2*>(&rs.x));
    float2 s1 = __half22float2(*reinterpret_cast<__half2*>(&rs.y));
    float4 bv = reinterpret_cast<const float4*>(bias)[lane];
    float rx = fmaxf(fmaf(acc.x, di, fmaf(s0.x, sw, bv.x)), 0.f);
    float ry = fmaxf(fmaf(acc.y, di, fmaf(s0.y, sw, bv.y)), 0.f);
    float rz = fmaxf(fmaf(acc.z, di, fmaf(s1.x, sw, bv.z)), 0.f);
    float rw = fmaxf(fmaf(acc.w, di, fmaf(s1.y, sw, bv.w)), 0.f);
    __half2 o0 = __floats2half2_rn(rx, ry);
    __half2 o1 = __floats2half2_rn(rz, rw);
    reinterpret_cast<uint2*>(g_aggh)[(size_t)gw * 32 + lane] =
        make_uint2(*reinterpret_cast<unsigned*>(&o0), *reinterpret_cast<unsigned*>(&o1));
}

__global__ void k_agg2(const float* __restrict__ bias, float* __restrict__ out, int N) {
    int gw   = (blockIdx.x * blockDim.x + threadIdx.x) >> 5;
    int lane = threadIdx.x & 31;
    if (gw >= N) return;
    const int start = g_rowstart[gw];
    const int end   = g_rowstart[gw + 1];

    const __half2* __restrict__ hp = reinterpret_cast<const __half2*>(g_h2h);
    float2 acc = make_float2(0.f, 0.f);

    #pragma unroll 4
    for (int e = start; e < end; e++) {
        int2  pr = g_epair[e];                 // uniform across warp
        float w  = __int_as_float(pr.y);
        float2 f = __half22float2(hp[(size_t)pr.x * 32 + lane]);
        acc.x = fmaf(f.x, w, acc.x);
        acc.y = fmaf(f.y, w, acc.y);
    }

    float di = g_dinv[gw];
    float sw = di * di;
    float2 fs = __half22float2(hp[(size_t)gw * 32 + lane]);
    float2 bv = reinterpret_cast<const float2*>(bias)[lane];
    float2 r;
    r.x = fmaf(acc.x, di, fmaf(fs.x, sw, bv.x));
    r.y = fmaf(acc.y, di, fmaf(fs.y, sw, bv.y));
    reinterpret_cast<float2*>(out)[(size_t)gw * 32 + lane] = r;
}

// ---------------- launch ------------------------------------------------------
extern "C" void kernel_launch(void* const* d_in, const int* in_sizes, int n_in,
                              void* d_out, int out_size) {
    const float* x     = (const float*)d_in[0];
    const void*  edges = d_in[1];                 // edge_index [2, E], int32 or int64
    const float* W1    = (const float*)d_in[2];
    const float* b1    = (const float*)d_in[3];
    const float* W2    = (const float*)d_in[4];
    const float* b2    = (const float*)d_in[5];
    float*       out   = (float*)d_out;

    const int E = in_sizes[1] / 2;     // 800000
    const int N = in_sizes[0] / FIN;   // 50000

    const int nb256_E = (E + 255) / 256;
    const int nb_scan = (N + SCAN_TILE - 1) / SCAN_TILE;

    // Fork-join: gemm1 (independent of edges) runs on a side stream in
    // parallel with the CSR build. Streams/events are host objects (no device
    // allocation); they intentionally outlive this call — capture-participating
    // streams must not be destroyed before the harness ends capture, and
    // kernel_launch is invoked only a handful of times.
    cudaStream_t s2;
    cudaEvent_t evFork, evJoin;
    cudaStreamCreateWithFlags(&s2, cudaStreamNonBlocking);
    cudaEventCreateWithFlags(&evFork, cudaEventDisableTiming);
    cudaEventCreateWithFlags(&evJoin, cudaEventDisableTiming);

    cudaEventRecord(evFork, 0);
    cudaStreamWaitEvent(s2, evFork, 0);
    k_gemm1<<<(N + 127) / 128, 256, 0, s2>>>(x, W1, N);    // side branch
    cudaEventRecord(evJoin, s2);

    // CSR build on the main (captured) stream
    k_deg_count<<<nb256_E, 256>>>(edges, E, N);
    k_scan_a   <<<nb_scan, 256>>>(N);
    k_scan_b   <<<nb_scan, 256>>>(N, E);
    k_perm     <<<nb256_E, 256>>>(edges, E, N);

    // join: agg1 needs both h1 (gemm1) and the CSR
    cudaStreamWaitEvent(0, evJoin, 0);
    k_agg1 <<<(N * 32 + 255) / 256, 256>>>(b1, N);

    // layer 2 (serial dependencies)
    k_gemm2<<<(N + 127) / 128, 256>>>(W2, N);
    k_agg2 <<<(N * 32 + 255) / 256, 256>>>(b2, out, N);
}